// round 13
// baseline (speedup 1.0000x reference)
#include <cuda_runtime.h>
#include <cuda_fp16.h>
#include <math.h>
#include <stdint.h>

#define NTOK 8192
#define DM   1024
#define DFF  4096
#define SEQ  2048
#define NB   4
#define NH   16
#define DKH  64

// ---------------- scratch (device globals: allocation-guard safe) ----------
__device__ __half g_h  [(size_t)NTOK * DM];
__device__ __half g_q  [(size_t)NTOK * DM];
__device__ __half g_k  [(size_t)NTOK * DM];
__device__ __half g_vt [(size_t)NB * DM * SEQ];   // V transposed: [b][col][s]
__device__ __half g_att[(size_t)NTOK * DM];
__device__ float  g_x1 [(size_t)NTOK * DM];
__device__ __half g_h2 [(size_t)NTOK * DM];
__device__ __half g_ff [(size_t)NTOK * DFF];
__device__ __half g_wqkvt[(size_t)3 * DM * DM];   // concat W{q,k,v}^T
__device__ __half g_wot[(size_t)DM * DM];
__device__ __half g_w1t[(size_t)DFF * DM];
__device__ __half g_w2t[(size_t)DM * DFF];

// ---------------- helpers ---------------------------------------------------
__device__ __forceinline__ uint32_t smem_u32(const void* p) {
    uint32_t a;
    asm("{ .reg .u64 t; cvta.to.shared.u64 t, %1; cvt.u32.u64 %0, t; }"
        : "=r"(a) : "l"(p));
    return a;
}
__device__ __forceinline__ void cp_async16(uint32_t dst, const void* src) {
    asm volatile("cp.async.cg.shared.global [%0], [%1], 16;" :: "r"(dst), "l"(src));
}
__device__ __forceinline__ void cp_commit() {
    asm volatile("cp.async.commit_group;" ::: "memory");
}
template <int N>
__device__ __forceinline__ void cp_wait() {
    asm volatile("cp.async.wait_group %0;" :: "n"(N) : "memory");
}
__device__ __forceinline__ void ldmatrix_x4(uint32_t* r, uint32_t addr) {
    asm volatile("ldmatrix.sync.aligned.m8n8.x4.shared.b16 {%0,%1,%2,%3}, [%4];"
                 : "=r"(r[0]), "=r"(r[1]), "=r"(r[2]), "=r"(r[3]) : "r"(addr));
}
__device__ __forceinline__ void mma_f16(float* c, const uint32_t* a, const uint32_t* b) {
    asm volatile(
        "mma.sync.aligned.m16n8k16.row.col.f32.f16.f16.f32 "
        "{%0,%1,%2,%3}, {%4,%5,%6,%7}, {%8,%9}, {%0,%1,%2,%3};"
        : "+f"(c[0]), "+f"(c[1]), "+f"(c[2]), "+f"(c[3])
        : "r"(a[0]), "r"(a[1]), "r"(a[2]), "r"(a[3]), "r"(b[0]), "r"(b[1]));
}
__device__ __forceinline__ uint32_t pack_h2(float lo, float hi) {
    __half2 h = __floats2half2_rn(lo, hi);
    return *(uint32_t*)&h;
}
__device__ __forceinline__ float gelu_exact(float v)
{
    return 0.5f * v * (1.0f + erff(v * 0.70710678118654752f));
}

// ---------------- merged weight transpose (6 jobs, 1 launch) ---------------
// job 0..3: [DM,DM] squares (Wq,Wk,Wv,Wo); job 4: W1 [DM,DFF]; job 5: W2 [DFF,DM]
__global__ void __launch_bounds__(256)
tr6_kernel(const float* __restrict__ Wq, const float* __restrict__ Wk,
           const float* __restrict__ Wv, const float* __restrict__ Wo,
           const float* __restrict__ W1, const float* __restrict__ W2,
           __half* __restrict__ wqkvt, __half* __restrict__ wot,
           __half* __restrict__ w1t,   __half* __restrict__ w2t)
{
    const int id = blockIdx.x;
    int job, base;
    if (id < 4096)      { job = id >> 10; base = id & 1023; }
    else if (id < 8192) { job = 4; base = id - 4096; }
    else                { job = 5; base = id - 8192; }

    const float* in; __half* out; int rows, cols, gx;
    switch (job) {
        case 0: in = Wq; out = wqkvt;                       rows = DM;  cols = DM;  gx = 32;  break;
        case 1: in = Wk; out = wqkvt + (size_t)DM * DM;     rows = DM;  cols = DM;  gx = 32;  break;
        case 2: in = Wv; out = wqkvt + (size_t)2 * DM * DM; rows = DM;  cols = DM;  gx = 32;  break;
        case 3: in = Wo; out = wot;                         rows = DM;  cols = DM;  gx = 32;  break;
        case 4: in = W1; out = w1t;                         rows = DM;  cols = DFF; gx = 128; break;
        default:in = W2; out = w2t;                         rows = DFF; cols = DM;  gx = 32;  break;
    }
    const int bx = base % gx, by = base / gx;

    __shared__ float t[32][33];
    const int tx = threadIdx.x & 31, ty = threadIdx.x >> 5;
    const int x  = bx * 32 + tx;
    const int y0 = by * 32;
    #pragma unroll
    for (int j = ty; j < 32; j += 8)
        t[j][tx] = in[(size_t)(y0 + j) * cols + x];
    __syncthreads();
    const int ox  = y0 + tx;
    const int oy0 = bx * 32;
    #pragma unroll
    for (int j = ty; j < 32; j += 8)
        out[(size_t)(oy0 + j) * rows + ox] = __float2half_rn(t[tx][j]);
}

// ---------------- LayerNorm (fp32 in -> fp16 out; only feeds GEMMs) --------
__global__ void __launch_bounds__(256)
ln_kernel(const float* __restrict__ x, const float* __restrict__ gam,
          const float* __restrict__ bet, __half* __restrict__ out)
{
    const int row = blockIdx.x;
    const float4 v = ((const float4*)(x + (size_t)row * DM))[threadIdx.x];
    float s = v.x + v.y + v.z + v.w;
    float q = v.x*v.x + v.y*v.y + v.z*v.z + v.w*v.w;
    #pragma unroll
    for (int o = 16; o; o >>= 1) {
        s += __shfl_xor_sync(0xffffffffu, s, o);
        q += __shfl_xor_sync(0xffffffffu, q, o);
    }
    __shared__ float ss[8], sq[8];
    const int w = threadIdx.x >> 5, l = threadIdx.x & 31;
    if (l == 0) { ss[w] = s; sq[w] = q; }
    __syncthreads();
    if (w == 0) {
        s = (l < 8) ? ss[l] : 0.f;
        q = (l < 8) ? sq[l] : 0.f;
        #pragma unroll
        for (int o = 4; o; o >>= 1) {
            s += __shfl_xor_sync(0xffffffffu, s, o);
            q += __shfl_xor_sync(0xffffffffu, q, o);
        }
        if (l == 0) { ss[0] = s; sq[0] = q; }
    }
    __syncthreads();
    const float mean = ss[0] * (1.f / DM);
    const float var  = sq[0] * (1.f / DM) - mean * mean;
    const float rstd = rsqrtf(var + 1e-5f);
    const float4 g4 = ((const float4*)gam)[threadIdx.x];
    const float4 b4 = ((const float4*)bet)[threadIdx.x];
    __half2* o2 = (__half2*)(out + (size_t)row * DM);
    o2[threadIdx.x * 2    ] = __floats2half2_rn((v.x - mean) * rstd * g4.x + b4.x,
                                                (v.y - mean) * rstd * g4.y + b4.y);
    o2[threadIdx.x * 2 + 1] = __floats2half2_rn((v.z - mean) * rstd * g4.z + b4.z,
                                                (v.w - mean) * rstd * g4.w + b4.w);
}

// ---------------- fp16 mma GEMM (K-chunk 64, 3-stage, ldmatrix) ------------
// C[NTOK, Mout] = A[NTOK, K] @ W[K, Mout] + bias (+gelu)(+res)
// 8 warps, warp tile 64x32. CTA tile 128x128, K-chunk 64.
// OUT: 0 = fp32 (+residual), 1 = fp16, 3 = fused QKV (writes g_q/g_k/g_vt)
#define PH 72                     // halfs per smem row (144B pitch; ldmatrix conflict-free)
#define STG_H (128 * PH)          // halfs per operand per stage
#define NSTG 3
#define GEMM_SMEM (NSTG * 2 * STG_H * 2)

template <int ACT, int OUT>
__global__ void __launch_bounds__(256, 2)
mma_gemm(const __half* __restrict__ A, const __half* __restrict__ Bt,
         const float* __restrict__ bias, const float* __restrict__ bias2,
         const float* __restrict__ bias3, const float* __restrict__ R,
         void* __restrict__ Cout, int K, int Mout)
{
    extern __shared__ __half hsm[];
    __half* Asm = hsm;
    __half* Bsm = hsm + NSTG * STG_H;

    const int tid  = threadIdx.x;
    const int lane = tid & 31, wid = tid >> 5;
    const int wm = (wid >> 2) * 64;
    const int wn = (wid & 3) * 32;
    const int qr = lane >> 2, qc = lane & 3;
    const int lm8 = lane >> 3;
    const int l8  = lane & 7;
    const int m0 = blockIdx.y * 128, n0 = blockIdx.x * 128;

    float c[4][4][4];
    #pragma unroll
    for (int i = 0; i < 4; i++)
        #pragma unroll
        for (int j = 0; j < 4; j++)
            #pragma unroll
            for (int e = 0; e < 4; e++) c[i][j][e] = 0.f;

    const int lrow = tid >> 1;            // 0..127
    const int lseg = (tid & 1) * 32;      // halfs (0 / 32)
    const __half* Ap = A  + (size_t)(m0 + lrow) * K + lseg;
    const __half* Bp = Bt + (size_t)(n0 + lrow) * K + lseg;

    const int NCH = K >> 6;               // K/64

    auto load_stage = [&](int st, int ch) {
        const int koff = ch * 64;
        __half* as = Asm + st * STG_H + lrow * PH + lseg;
        __half* bs = Bsm + st * STG_H + lrow * PH + lseg;
        #pragma unroll
        for (int u = 0; u < 4; u++) {
            cp_async16(smem_u32(as + u * 8), Ap + koff + u * 8);
            cp_async16(smem_u32(bs + u * 8), Bp + koff + u * 8);
        }
        cp_commit();
    };

    load_stage(0, 0);
    load_stage(1, 1);

    const int a_ro = ((lm8 & 1) << 3) + l8;
    const int a_co = (lm8 >> 1) << 3;
    const int b_ro = ((lm8 >> 1) << 3) + l8;
    const int b_co = (lm8 & 1) << 3;

    for (int ch = 0; ch < NCH; ch++) {
        const int buf = ch % NSTG;
        cp_wait<1>();
        __syncthreads();

        // issue next stage BEFORE compute (writes (ch+2)%3 == (ch-1)%3,
        // last read at iter ch-1, ordered by the barrier above)
        if (ch + 2 < NCH) load_stage((ch + 2) % NSTG, ch + 2);
        else              cp_commit();

        const __half* as = Asm + buf * STG_H;
        const __half* bs = Bsm + buf * STG_H;

        #pragma unroll
        for (int ks = 0; ks < 4; ks++) {
            uint32_t a[4][4], b[4][2];
            #pragma unroll
            for (int mt = 0; mt < 4; mt++)
                ldmatrix_x4(a[mt],
                    smem_u32(as + (wm + mt * 16 + a_ro) * PH + ks * 16 + a_co));
            #pragma unroll
            for (int np = 0; np < 2; np++) {
                uint32_t r[4];
                ldmatrix_x4(r,
                    smem_u32(bs + (wn + np * 16 + b_ro) * PH + ks * 16 + b_co));
                b[2*np    ][0] = r[0]; b[2*np    ][1] = r[1];
                b[2*np + 1][0] = r[2]; b[2*np + 1][1] = r[3];
            }
            #pragma unroll
            for (int mt = 0; mt < 4; mt++)
                #pragma unroll
                for (int nt = 0; nt < 4; nt++)
                    mma_f16(c[mt][nt], a[mt], b[nt]);
        }
    }

    // ---- epilogue ----
    if (OUT == 3) {
        const int seg   = n0 >> 10;
        const int nbase = (n0 & 1023) + wn;
        const float* bp = (seg == 0) ? bias : (seg == 1 ? bias2 : bias3);
        #pragma unroll
        for (int mt = 0; mt < 4; mt++) {
            #pragma unroll
            for (int half_ = 0; half_ < 2; half_++) {
                const int gm = m0 + wm + mt * 16 + qr + half_ * 8;
                #pragma unroll
                for (int nt = 0; nt < 4; nt++) {
                    const int col = nbase + nt * 8 + qc * 2;
                    const float v0 = c[mt][nt][half_ * 2 + 0] + bp[col];
                    const float v1 = c[mt][nt][half_ * 2 + 1] + bp[col + 1];
                    if (seg == 0) {
                        *(__half2*)&g_q[(size_t)gm * DM + col] = __floats2half2_rn(v0, v1);
                    } else if (seg == 1) {
                        *(__half2*)&g_k[(size_t)gm * DM + col] = __floats2half2_rn(v0, v1);
                    } else {
                        const int bb = gm >> 11, s = gm & 2047;
                        g_vt[((size_t)bb * DM + col    ) * SEQ + s] = __float2half_rn(v0);
                        g_vt[((size_t)bb * DM + col + 1) * SEQ + s] = __float2half_rn(v1);
                    }
                }
            }
        }
    } else {
        #pragma unroll
        for (int mt = 0; mt < 4; mt++) {
            #pragma unroll
            for (int half_ = 0; half_ < 2; half_++) {
                const int gm = m0 + wm + mt * 16 + qr + half_ * 8;
                #pragma unroll
                for (int nt = 0; nt < 4; nt++) {
                    const int col = n0 + wn + nt * 8 + qc * 2;
                    float v0 = c[mt][nt][half_ * 2 + 0] + bias[col];
                    float v1 = c[mt][nt][half_ * 2 + 1] + bias[col + 1];
                    if (ACT == 1) { v0 = gelu_exact(v0); v1 = gelu_exact(v1); }
                    if (OUT == 0) {
                        const float2 rv = *(const float2*)&R[(size_t)gm * Mout + col];
                        *(float2*)((float*)Cout + (size_t)gm * Mout + col) =
                            make_float2(v0 + rv.x, v1 + rv.y);
                    } else {
                        *(__half2*)((__half*)Cout + (size_t)gm * Mout + col) =
                            __floats2half2_rn(v0, v1);
                    }
                }
            }
        }
    }
}

// ---------------- fp16 mma flash attention (ldmatrix) ----------------------
#define PT 72
#define T_H (64 * PT)
#define ATTN_SMEM ((T_H + 2 * T_H + 2 * T_H) * 2 + 2 * 64 * 4)

__global__ void __launch_bounds__(128, 3)
attn_kernel(const __half* __restrict__ Q, const __half* __restrict__ K,
            const __half* __restrict__ Vt, const int* __restrict__ mask,
            __half* __restrict__ O)
{
    extern __shared__ __half asm_[];
    __half* Qs = asm_;
    __half* Ks = asm_ + T_H;
    __half* Vs = asm_ + 3 * T_H;
    int*    mk = (int*)(asm_ + 5 * T_H);

    const int tid  = threadIdx.x;
    const int lane = tid & 31, wid = tid >> 5;
    const int qr = lane >> 2, qc = lane & 3;
    const int lm8 = lane >> 3, l8 = lane & 7;
    const int wm = wid * 16;
    const int b  = blockIdx.z, hh = blockIdx.y;
    const int q0 = blockIdx.x * 64;
    const int bS = b * SEQ;
    const int hoff = hh * DKH;

    const int lrow = tid >> 1;
    const int lseg = (tid & 1) * 32;

    {
        const __half* src = Q + (size_t)(bS + q0 + lrow) * DM + hoff + lseg;
        uint32_t dst = smem_u32(Qs + lrow * PT + lseg);
        #pragma unroll
        for (int u = 0; u < 4; u++) cp_async16(dst + u * 16, src + u * 8);
        cp_commit();
    }

    const __half* VtBase = Vt + ((size_t)b * DM + hoff) * SEQ;

    auto load_kv = [&](int buf, int kv0) {
        const __half* ks = K + (size_t)(bS + kv0 + lrow) * DM + hoff + lseg;
        const __half* vs = VtBase + (size_t)lrow * SEQ + kv0 + lseg;
        uint32_t dk = smem_u32(Ks + buf * T_H + lrow * PT + lseg);
        uint32_t dv = smem_u32(Vs + buf * T_H + lrow * PT + lseg);
        #pragma unroll
        for (int u = 0; u < 4; u++) {
            cp_async16(dk + u * 16, ks + u * 8);
            cp_async16(dv + u * 16, vs + u * 8);
        }
        if (tid < 16)
            cp_async16(smem_u32(mk + buf * 64 + tid * 4), mask + bS + kv0 + tid * 4);
    };

    load_kv(0, 0);
    cp_commit();
    cp_wait<0>();
    __syncthreads();

    const int a_ro = ((lm8 & 1) << 3) + l8;
    const int a_co = (lm8 >> 1) << 3;
    const int b_ro = ((lm8 >> 1) << 3) + l8;
    const int b_co = (lm8 & 1) << 3;

    uint32_t a_q[4][4];
    #pragma unroll
    for (int ks = 0; ks < 4; ks++)
        ldmatrix_x4(a_q[ks], smem_u32(Qs + (wm + a_ro) * PT + ks * 16 + a_co));

    float c_o[8][4];
    #pragma unroll
    for (int nt = 0; nt < 8; nt++)
        #pragma unroll
        for (int e = 0; e < 4; e++) c_o[nt][e] = 0.f;
    float m0r = -1e30f, m1r = -1e30f, l0r = 0.f, l1r = 0.f;

    const int NT = SEQ / 64;
    for (int t = 0; t < NT; t++) {
        const int buf = t & 1;
        if (t + 1 < NT) { load_kv(buf ^ 1, (t + 1) * 64); cp_commit(); }

        float c_s[8][4];
        #pragma unroll
        for (int nt = 0; nt < 8; nt++)
            #pragma unroll
            for (int e = 0; e < 4; e++) c_s[nt][e] = 0.f;

        const __half* kb = Ks + buf * T_H;
        #pragma unroll
        for (int ks = 0; ks < 4; ks++) {
            uint32_t bb[8][2];
            #pragma unroll
            for (int np = 0; np < 4; np++) {
                uint32_t r[4];
                ldmatrix_x4(r, smem_u32(kb + (np * 16 + b_ro) * PT + ks * 16 + b_co));
                bb[2*np    ][0] = r[0]; bb[2*np    ][1] = r[1];
                bb[2*np + 1][0] = r[2]; bb[2*np + 1][1] = r[3];
            }
            #pragma unroll
            for (int nt = 0; nt < 8; nt++)
                mma_f16(c_s[nt], a_q[ks], bb[nt]);
        }

        float mx0 = -1e30f, mx1 = -1e30f;
        #pragma unroll
        for (int nt = 0; nt < 8; nt++) {
            const int c0 = nt * 8 + qc * 2;
            c_s[nt][0] = mk[buf * 64 + c0    ] ? c_s[nt][0] * 0.125f : -1e9f;
            c_s[nt][1] = mk[buf * 64 + c0 + 1] ? c_s[nt][1] * 0.125f : -1e9f;
            c_s[nt][2] = mk[buf * 64 + c0    ] ? c_s[nt][2] * 0.125f : -1e9f;
            c_s[nt][3] = mk[buf * 64 + c0 + 1] ? c_s[nt][3] * 0.125f : -1e9f;
            mx0 = fmaxf(mx0, fmaxf(c_s[nt][0], c_s[nt][1]));
            mx1 = fmaxf(mx1, fmaxf(c_s[nt][2], c_s[nt][3]));
        }
        #pragma unroll
        for (int off = 1; off < 4; off <<= 1) {
            mx0 = fmaxf(mx0, __shfl_xor_sync(0xffffffffu, mx0, off));
            mx1 = fmaxf(mx1, __shfl_xor_sync(0xffffffffu, mx1, off));
        }
        const float mn0 = fmaxf(m0r, mx0), mn1 = fmaxf(m1r, mx1);
        const float al0 = __expf(m0r - mn0), al1 = __expf(m1r - mn1);
        float s0 = 0.f, s1 = 0.f;
        #pragma unroll
        for (int nt = 0; nt < 8; nt++) {
            c_s[nt][0] = __expf(c_s[nt][0] - mn0);
            c_s[nt][1] = __expf(c_s[nt][1] - mn0);
            c_s[nt][2] = __expf(c_s[nt][2] - mn1);
            c_s[nt][3] = __expf(c_s[nt][3] - mn1);
            s0 += c_s[nt][0] + c_s[nt][1];
            s1 += c_s[nt][2] + c_s[nt][3];
        }
        #pragma unroll
        for (int off = 1; off < 4; off <<= 1) {
            s0 += __shfl_xor_sync(0xffffffffu, s0, off);
            s1 += __shfl_xor_sync(0xffffffffu, s1, off);
        }
        l0r = l0r * al0 + s0;  m0r = mn0;
        l1r = l1r * al1 + s1;  m1r = mn1;
        #pragma unroll
        for (int nt = 0; nt < 8; nt++) {
            c_o[nt][0] *= al0; c_o[nt][1] *= al0;
            c_o[nt][2] *= al1; c_o[nt][3] *= al1;
        }

        uint32_t ap[4][4];
        #pragma unroll
        for (int ks = 0; ks < 4; ks++) {
            ap[ks][0] = pack_h2(c_s[2*ks    ][0], c_s[2*ks    ][1]);
            ap[ks][1] = pack_h2(c_s[2*ks    ][2], c_s[2*ks    ][3]);
            ap[ks][2] = pack_h2(c_s[2*ks + 1][0], c_s[2*ks + 1][1]);
            ap[ks][3] = pack_h2(c_s[2*ks + 1][2], c_s[2*ks + 1][3]);
        }

        const __half* vb = Vs + buf * T_H;
        #pragma unroll
        for (int ks = 0; ks < 4; ks++) {
            uint32_t bb[8][2];
            #pragma unroll
            for (int np = 0; np < 4; np++) {
                uint32_t r[4];
                ldmatrix_x4(r, smem_u32(vb + (np * 16 + b_ro) * PT + ks * 16 + b_co));
                bb[2*np    ][0] = r[0]; bb[2*np    ][1] = r[1];
                bb[2*np + 1][0] = r[2]; bb[2*np + 1][1] = r[3];
            }
            #pragma unroll
            for (int nt = 0; nt < 8; nt++)
                mma_f16(c_o[nt], ap[ks], bb[nt]);
        }

        if (t + 1 < NT) cp_wait<0>();
        __syncthreads();
    }

    const float i0 = 1.f / l0r, i1 = 1.f / l1r;
    #pragma unroll
    for (int nt = 0; nt < 8; nt++) {
        const size_t r0 = (size_t)(bS + q0 + wm + qr);
        const int col = hoff + nt * 8 + qc * 2;
        *(__half2*)&O[r0 * DM + col] =
            __floats2half2_rn(c_o[nt][0] * i0, c_o[nt][1] * i0);
        *(__half2*)&O[(r0 + 8) * DM + col] =
            __floats2half2_rn(c_o[nt][2] * i1, c_o[nt][3] * i1);
    }
}

// ---------------- launch ---------------------------------------------------
extern "C" void kernel_launch(void* const* d_in, const int* in_sizes, int n_in,
                              void* d_out, int out_size)
{
    const float* x    = (const float*)d_in[0];
    const int*   mask = (const int*)  d_in[1];
    const float* Wq   = (const float*)d_in[2];
    const float* bq   = (const float*)d_in[3];
    const float* Wk   = (const float*)d_in[4];
    const float* bk   = (const float*)d_in[5];
    const float* Wv   = (const float*)d_in[6];
    const float* bv   = (const float*)d_in[7];
    const float* Wo   = (const float*)d_in[8];
    const float* bo   = (const float*)d_in[9];
    const float* W1   = (const float*)d_in[10];
    const float* b1   = (const float*)d_in[11];
    const float* W2   = (const float*)d_in[12];
    const float* b2   = (const float*)d_in[13];
    const float* g1   = (const float*)d_in[14];
    const float* be1  = (const float*)d_in[15];
    const float* g2   = (const float*)d_in[16];
    const float* be2  = (const float*)d_in[17];
    float* out = (float*)d_out;

    __half *h, *q, *k, *vt, *att, *h2, *ff;
    float  *x1;
    __half *wqkvt, *wot, *w1t, *w2t;
    cudaGetSymbolAddress((void**)&h,     g_h);
    cudaGetSymbolAddress((void**)&q,     g_q);
    cudaGetSymbolAddress((void**)&k,     g_k);
    cudaGetSymbolAddress((void**)&vt,    g_vt);
    cudaGetSymbolAddress((void**)&att,   g_att);
    cudaGetSymbolAddress((void**)&x1,    g_x1);
    cudaGetSymbolAddress((void**)&h2,    g_h2);
    cudaGetSymbolAddress((void**)&ff,    g_ff);
    cudaGetSymbolAddress((void**)&wqkvt, g_wqkvt);
    cudaGetSymbolAddress((void**)&wot,   g_wot);
    cudaGetSymbolAddress((void**)&w1t,   g_w1t);
    cudaGetSymbolAddress((void**)&w2t,   g_w2t);

    cudaFuncSetAttribute(attn_kernel,
                         cudaFuncAttributeMaxDynamicSharedMemorySize, ATTN_SMEM);
    cudaFuncSetAttribute(mma_gemm<0, 0>,
                         cudaFuncAttributeMaxDynamicSharedMemorySize, GEMM_SMEM);
    cudaFuncSetAttribute(mma_gemm<0, 1>,
                         cudaFuncAttributeMaxDynamicSharedMemorySize, GEMM_SMEM);
    cudaFuncSetAttribute(mma_gemm<0, 3>,
                         cudaFuncAttributeMaxDynamicSharedMemorySize, GEMM_SMEM);
    cudaFuncSetAttribute(mma_gemm<1, 1>,
                         cudaFuncAttributeMaxDynamicSharedMemorySize, GEMM_SMEM);

    // all 6 weight transposes in one launch
    tr6_kernel<<<12288, 256>>>(Wq, Wk, Wv, Wo, W1, W2, wqkvt, wot, w1t, w2t);

    ln_kernel<<<NTOK, 256>>>(x, g1, be1, h);
    // fused Q/K/V projection (writes g_q, g_k, g_vt directly)
    mma_gemm<0, 3><<<dim3(3 * DM / 128, NTOK / 128), 256, GEMM_SMEM>>>(
        h, wqkvt, bq, bk, bv, nullptr, nullptr, DM, 3 * DM);
    attn_kernel<<<dim3(SEQ / 64, NH, NB), 128, ATTN_SMEM>>>(q, k, vt, mask, att);
    mma_gemm<0, 0><<<dim3(DM / 128, NTOK / 128), 256, GEMM_SMEM>>>(
        att, wot, bo, nullptr, nullptr, x, x1, DM, DM);
    ln_kernel<<<NTOK, 256>>>(x1, g2, be2, h2);
    mma_gemm<1, 1><<<dim3(DFF / 128, NTOK / 128), 256, GEMM_SMEM>>>(
        h2, w1t, b1, nullptr, nullptr, nullptr, ff, DM, DFF);
    mma_gemm<0, 0><<<dim3(DM / 128, NTOK / 128), 256, GEMM_SMEM>>>(
        ff, w2t, b2, nullptr, nullptr, x1, out, DFF, DM);
}

// round 14
// speedup vs baseline: 1.1170x; 1.1170x over previous
#include <cuda_runtime.h>
#include <cuda_fp16.h>
#include <math.h>
#include <stdint.h>

#define NTOK 8192
#define DM   1024
#define DFF  4096
#define SEQ  2048
#define NB   4
#define NH   16
#define DKH  64

// ---------------- scratch (device globals: allocation-guard safe) ----------
__device__ __half g_h  [(size_t)NTOK * DM];
__device__ __half g_q  [(size_t)NTOK * DM];
__device__ __half g_k  [(size_t)NTOK * DM];
__device__ __half g_vt [(size_t)NB * DM * SEQ];   // V transposed: [b][col][s]
__device__ __half g_att[(size_t)NTOK * DM];
__device__ float  g_x1 [(size_t)NTOK * DM];
__device__ __half g_h2 [(size_t)NTOK * DM];
__device__ __half g_ff [(size_t)NTOK * DFF];
__device__ __half g_wqkvt[(size_t)3 * DM * DM];   // concat W{q,k,v}^T
__device__ __half g_wot[(size_t)DM * DM];
__device__ __half g_w1t[(size_t)DFF * DM];
__device__ __half g_w2t[(size_t)DM * DFF];

// ---------------- helpers ---------------------------------------------------
__device__ __forceinline__ uint32_t smem_u32(const void* p) {
    uint32_t a;
    asm("{ .reg .u64 t; cvta.to.shared.u64 t, %1; cvt.u32.u64 %0, t; }"
        : "=r"(a) : "l"(p));
    return a;
}
__device__ __forceinline__ void cp_async16(uint32_t dst, const void* src) {
    asm volatile("cp.async.cg.shared.global [%0], [%1], 16;" :: "r"(dst), "l"(src));
}
__device__ __forceinline__ void cp_commit() {
    asm volatile("cp.async.commit_group;" ::: "memory");
}
template <int N>
__device__ __forceinline__ void cp_wait() {
    asm volatile("cp.async.wait_group %0;" :: "n"(N) : "memory");
}
__device__ __forceinline__ void ldmatrix_x4(uint32_t* r, uint32_t addr) {
    asm volatile("ldmatrix.sync.aligned.m8n8.x4.shared.b16 {%0,%1,%2,%3}, [%4];"
                 : "=r"(r[0]), "=r"(r[1]), "=r"(r[2]), "=r"(r[3]) : "r"(addr));
}
__device__ __forceinline__ void mma_f16(float* c, const uint32_t* a, const uint32_t* b) {
    asm volatile(
        "mma.sync.aligned.m16n8k16.row.col.f32.f16.f16.f32 "
        "{%0,%1,%2,%3}, {%4,%5,%6,%7}, {%8,%9}, {%0,%1,%2,%3};"
        : "+f"(c[0]), "+f"(c[1]), "+f"(c[2]), "+f"(c[3])
        : "r"(a[0]), "r"(a[1]), "r"(a[2]), "r"(a[3]), "r"(b[0]), "r"(b[1]));
}
__device__ __forceinline__ uint32_t pack_h2(float lo, float hi) {
    __half2 h = __floats2half2_rn(lo, hi);
    return *(uint32_t*)&h;
}
__device__ __forceinline__ float gelu_exact(float v)
{
    return 0.5f * v * (1.0f + erff(v * 0.70710678118654752f));
}

// ---------------- merged weight transpose (6 jobs, 1 launch) ---------------
// job 0..3: [DM,DM] squares (Wq,Wk,Wv,Wo); job 4: W1 [DM,DFF]; job 5: W2 [DFF,DM]
__global__ void __launch_bounds__(256)
tr6_kernel(const float* __restrict__ Wq, const float* __restrict__ Wk,
           const float* __restrict__ Wv, const float* __restrict__ Wo,
           const float* __restrict__ W1, const float* __restrict__ W2,
           __half* __restrict__ wqkvt, __half* __restrict__ wot,
           __half* __restrict__ w1t,   __half* __restrict__ w2t)
{
    const int id = blockIdx.x;
    int job, base;
    if (id < 4096)      { job = id >> 10; base = id & 1023; }
    else if (id < 8192) { job = 4; base = id - 4096; }
    else                { job = 5; base = id - 8192; }

    const float* in; __half* out; int rows, cols, gx;
    switch (job) {
        case 0: in = Wq; out = wqkvt;                       rows = DM;  cols = DM;  gx = 32;  break;
        case 1: in = Wk; out = wqkvt + (size_t)DM * DM;     rows = DM;  cols = DM;  gx = 32;  break;
        case 2: in = Wv; out = wqkvt + (size_t)2 * DM * DM; rows = DM;  cols = DM;  gx = 32;  break;
        case 3: in = Wo; out = wot;                         rows = DM;  cols = DM;  gx = 32;  break;
        case 4: in = W1; out = w1t;                         rows = DM;  cols = DFF; gx = 128; break;
        default:in = W2; out = w2t;                         rows = DFF; cols = DM;  gx = 32;  break;
    }
    const int bx = base % gx, by = base / gx;

    __shared__ float t[32][33];
    const int tx = threadIdx.x & 31, ty = threadIdx.x >> 5;
    const int x  = bx * 32 + tx;
    const int y0 = by * 32;
    #pragma unroll
    for (int j = ty; j < 32; j += 8)
        t[j][tx] = in[(size_t)(y0 + j) * cols + x];
    __syncthreads();
    const int ox  = y0 + tx;
    const int oy0 = bx * 32;
    #pragma unroll
    for (int j = ty; j < 32; j += 8)
        out[(size_t)(oy0 + j) * rows + ox] = __float2half_rn(t[tx][j]);
}

// ---------------- LayerNorm (fp32 in -> fp16 out; only feeds GEMMs) --------
__global__ void __launch_bounds__(256)
ln_kernel(const float* __restrict__ x, const float* __restrict__ gam,
          const float* __restrict__ bet, __half* __restrict__ out)
{
    const int row = blockIdx.x;
    const float4 v = ((const float4*)(x + (size_t)row * DM))[threadIdx.x];
    float s = v.x + v.y + v.z + v.w;
    float q = v.x*v.x + v.y*v.y + v.z*v.z + v.w*v.w;
    #pragma unroll
    for (int o = 16; o; o >>= 1) {
        s += __shfl_xor_sync(0xffffffffu, s, o);
        q += __shfl_xor_sync(0xffffffffu, q, o);
    }
    __shared__ float ss[8], sq[8];
    const int w = threadIdx.x >> 5, l = threadIdx.x & 31;
    if (l == 0) { ss[w] = s; sq[w] = q; }
    __syncthreads();
    if (w == 0) {
        s = (l < 8) ? ss[l] : 0.f;
        q = (l < 8) ? sq[l] : 0.f;
        #pragma unroll
        for (int o = 4; o; o >>= 1) {
            s += __shfl_xor_sync(0xffffffffu, s, o);
            q += __shfl_xor_sync(0xffffffffu, q, o);
        }
        if (l == 0) { ss[0] = s; sq[0] = q; }
    }
    __syncthreads();
    const float mean = ss[0] * (1.f / DM);
    const float var  = sq[0] * (1.f / DM) - mean * mean;
    const float rstd = rsqrtf(var + 1e-5f);
    const float4 g4 = ((const float4*)gam)[threadIdx.x];
    const float4 b4 = ((const float4*)bet)[threadIdx.x];
    __half2* o2 = (__half2*)(out + (size_t)row * DM);
    o2[threadIdx.x * 2    ] = __floats2half2_rn((v.x - mean) * rstd * g4.x + b4.x,
                                                (v.y - mean) * rstd * g4.y + b4.y);
    o2[threadIdx.x * 2 + 1] = __floats2half2_rn((v.z - mean) * rstd * g4.z + b4.z,
                                                (v.w - mean) * rstd * g4.w + b4.w);
}

// ---------------- fp16 mma GEMM (4-stage cp.async + ldmatrix) --------------
// C[NTOK, Mout] = A[NTOK, K] @ W[K, Mout] + bias (+gelu)(+res)
// 8 warps, warp tile 64x32. CTA tile 128x128, K-chunk 32 (R12 best config).
// OUT: 0 = fp32 (+residual), 1 = fp16, 3 = fused QKV (writes g_q/g_k/g_vt)
#define PH 40                     // halfs per smem row (80B pitch)
#define STG_H (128 * PH)          // halfs per operand per stage
#define NSTG 4
#define GEMM_SMEM (NSTG * 2 * STG_H * 2)

template <int ACT, int OUT>
__global__ void __launch_bounds__(256, 2)
mma_gemm(const __half* __restrict__ A, const __half* __restrict__ Bt,
         const float* __restrict__ bias, const float* __restrict__ bias2,
         const float* __restrict__ bias3, const float* __restrict__ R,
         void* __restrict__ Cout, int K, int Mout)
{
    extern __shared__ __half hsm[];
    __half* Asm = hsm;
    __half* Bsm = hsm + NSTG * STG_H;

    const int tid  = threadIdx.x;
    const int lane = tid & 31, wid = tid >> 5;
    const int wm = (wid >> 2) * 64;
    const int wn = (wid & 3) * 32;
    const int qr = lane >> 2, qc = lane & 3;
    const int lm8 = lane >> 3;
    const int l8  = lane & 7;
    const int m0 = blockIdx.y * 128, n0 = blockIdx.x * 128;

    float c[4][4][4];
    #pragma unroll
    for (int i = 0; i < 4; i++)
        #pragma unroll
        for (int j = 0; j < 4; j++)
            #pragma unroll
            for (int e = 0; e < 4; e++) c[i][j][e] = 0.f;

    const int lrow = tid >> 1;
    const int lseg = (tid & 1) * 16;
    const __half* Ap = A  + (size_t)(m0 + lrow) * K + lseg;
    const __half* Bp = Bt + (size_t)(n0 + lrow) * K + lseg;

    const int NCH = K >> 5;

    auto load_stage = [&](int st, int ch) {
        const int koff = ch * 32;
        __half* as = Asm + st * STG_H + lrow * PH + lseg;
        __half* bs = Bsm + st * STG_H + lrow * PH + lseg;
        cp_async16(smem_u32(as),     Ap + koff);
        cp_async16(smem_u32(as + 8), Ap + koff + 8);
        cp_async16(smem_u32(bs),     Bp + koff);
        cp_async16(smem_u32(bs + 8), Bp + koff + 8);
        cp_commit();
    };

    load_stage(0, 0);
    load_stage(1, 1);
    load_stage(2, 2);

    const int a_ro = ((lm8 & 1) << 3) + l8;
    const int a_co = (lm8 >> 1) << 3;
    const int b_ro = ((lm8 >> 1) << 3) + l8;
    const int b_co = (lm8 & 1) << 3;

    for (int ch = 0; ch < NCH; ch++) {
        const int buf = ch % NSTG;
        cp_wait<2>();
        __syncthreads();

        // issue next stage BEFORE compute: depth-3 latency hiding.
        // Writes buf (ch+3)%4 == (ch-1)%4, last read at iter ch-1, ordered by
        // the barrier above.
        if (ch + 3 < NCH) load_stage((ch + 3) % NSTG, ch + 3);
        else              cp_commit();

        const __half* as = Asm + buf * STG_H;
        const __half* bs = Bsm + buf * STG_H;

        #pragma unroll
        for (int ks = 0; ks < 2; ks++) {
            uint32_t a[4][4], b[4][2];
            #pragma unroll
            for (int mt = 0; mt < 4; mt++)
                ldmatrix_x4(a[mt],
                    smem_u32(as + (wm + mt * 16 + a_ro) * PH + ks * 16 + a_co));
            #pragma unroll
            for (int np = 0; np < 2; np++) {
                uint32_t r[4];
                ldmatrix_x4(r,
                    smem_u32(bs + (wn + np * 16 + b_ro) * PH + ks * 16 + b_co));
                b[2*np    ][0] = r[0]; b[2*np    ][1] = r[1];
                b[2*np + 1][0] = r[2]; b[2*np + 1][1] = r[3];
            }
            #pragma unroll
            for (int mt = 0; mt < 4; mt++)
                #pragma unroll
                for (int nt = 0; nt < 4; nt++)
                    mma_f16(c[mt][nt], a[mt], b[nt]);
        }
    }

    // ---- epilogue ----
    if (OUT == 3) {
        const int seg   = n0 >> 10;
        const int nbase = (n0 & 1023) + wn;
        const float* bp = (seg == 0) ? bias : (seg == 1 ? bias2 : bias3);
        #pragma unroll
        for (int mt = 0; mt < 4; mt++) {
            #pragma unroll
            for (int half_ = 0; half_ < 2; half_++) {
                const int gm = m0 + wm + mt * 16 + qr + half_ * 8;
                #pragma unroll
                for (int nt = 0; nt < 4; nt++) {
                    const int col = nbase + nt * 8 + qc * 2;
                    const float v0 = c[mt][nt][half_ * 2 + 0] + bp[col];
                    const float v1 = c[mt][nt][half_ * 2 + 1] + bp[col + 1];
                    if (seg == 0) {
                        *(__half2*)&g_q[(size_t)gm * DM + col] = __floats2half2_rn(v0, v1);
                    } else if (seg == 1) {
                        *(__half2*)&g_k[(size_t)gm * DM + col] = __floats2half2_rn(v0, v1);
                    } else {
                        const int bb = gm >> 11, s = gm & 2047;
                        g_vt[((size_t)bb * DM + col    ) * SEQ + s] = __float2half_rn(v0);
                        g_vt[((size_t)bb * DM + col + 1) * SEQ + s] = __float2half_rn(v1);
                    }
                }
            }
        }
    } else {
        #pragma unroll
        for (int mt = 0; mt < 4; mt++) {
            #pragma unroll
            for (int half_ = 0; half_ < 2; half_++) {
                const int gm = m0 + wm + mt * 16 + qr + half_ * 8;
                #pragma unroll
                for (int nt = 0; nt < 4; nt++) {
                    const int col = n0 + wn + nt * 8 + qc * 2;
                    float v0 = c[mt][nt][half_ * 2 + 0] + bias[col];
                    float v1 = c[mt][nt][half_ * 2 + 1] + bias[col + 1];
                    if (ACT == 1) { v0 = gelu_exact(v0); v1 = gelu_exact(v1); }
                    if (OUT == 0) {
                        const float2 rv = *(const float2*)&R[(size_t)gm * Mout + col];
                        *(float2*)((float*)Cout + (size_t)gm * Mout + col) =
                            make_float2(v0 + rv.x, v1 + rv.y);
                    } else {
                        *(__half2*)((__half*)Cout + (size_t)gm * Mout + col) =
                            __floats2half2_rn(v0, v1);
                    }
                }
            }
        }
    }
}

// ---------------- fp16 mma flash attention (ldmatrix) ----------------------
#define PT 72
#define T_H (64 * PT)
#define ATTN_SMEM ((T_H + 2 * T_H + 2 * T_H) * 2 + 2 * 64 * 4)

__global__ void __launch_bounds__(128)
attn_kernel(const __half* __restrict__ Q, const __half* __restrict__ K,
            const __half* __restrict__ Vt, const int* __restrict__ mask,
            __half* __restrict__ O)
{
    extern __shared__ __half asm_[];
    __half* Qs = asm_;
    __half* Ks = asm_ + T_H;
    __half* Vs = asm_ + 3 * T_H;
    int*    mk = (int*)(asm_ + 5 * T_H);

    const int tid  = threadIdx.x;
    const int lane = tid & 31, wid = tid >> 5;
    const int qr = lane >> 2, qc = lane & 3;
    const int lm8 = lane >> 3, l8 = lane & 7;
    const int wm = wid * 16;
    const int b  = blockIdx.z, hh = blockIdx.y;
    const int q0 = blockIdx.x * 64;
    const int bS = b * SEQ;
    const int hoff = hh * DKH;

    const int lrow = tid >> 1;
    const int lseg = (tid & 1) * 32;

    {
        const __half* src = Q + (size_t)(bS + q0 + lrow) * DM + hoff + lseg;
        uint32_t dst = smem_u32(Qs + lrow * PT + lseg);
        #pragma unroll
        for (int u = 0; u < 4; u++) cp_async16(dst + u * 16, src + u * 8);
        cp_commit();
    }

    const __half* VtBase = Vt + ((size_t)b * DM + hoff) * SEQ;

    auto load_kv = [&](int buf, int kv0) {
        const __half* ks = K + (size_t)(bS + kv0 + lrow) * DM + hoff + lseg;
        const __half* vs = VtBase + (size_t)lrow * SEQ + kv0 + lseg;
        uint32_t dk = smem_u32(Ks + buf * T_H + lrow * PT + lseg);
        uint32_t dv = smem_u32(Vs + buf * T_H + lrow * PT + lseg);
        #pragma unroll
        for (int u = 0; u < 4; u++) {
            cp_async16(dk + u * 16, ks + u * 8);
            cp_async16(dv + u * 16, vs + u * 8);
        }
        if (tid < 16)
            cp_async16(smem_u32(mk + buf * 64 + tid * 4), mask + bS + kv0 + tid * 4);
    };

    load_kv(0, 0);
    cp_commit();
    cp_wait<0>();
    __syncthreads();

    const int a_ro = ((lm8 & 1) << 3) + l8;
    const int a_co = (lm8 >> 1) << 3;
    const int b_ro = ((lm8 >> 1) << 3) + l8;
    const int b_co = (lm8 & 1) << 3;

    uint32_t a_q[4][4];
    #pragma unroll
    for (int ks = 0; ks < 4; ks++)
        ldmatrix_x4(a_q[ks], smem_u32(Qs + (wm + a_ro) * PT + ks * 16 + a_co));

    float c_o[8][4];
    #pragma unroll
    for (int nt = 0; nt < 8; nt++)
        #pragma unroll
        for (int e = 0; e < 4; e++) c_o[nt][e] = 0.f;
    float m0r = -1e30f, m1r = -1e30f, l0r = 0.f, l1r = 0.f;

    const int NT = SEQ / 64;
    for (int t = 0; t < NT; t++) {
        const int buf = t & 1;
        if (t + 1 < NT) { load_kv(buf ^ 1, (t + 1) * 64); cp_commit(); }

        float c_s[8][4];
        #pragma unroll
        for (int nt = 0; nt < 8; nt++)
            #pragma unroll
            for (int e = 0; e < 4; e++) c_s[nt][e] = 0.f;

        const __half* kb = Ks + buf * T_H;
        #pragma unroll
        for (int ks = 0; ks < 4; ks++) {
            uint32_t bb[8][2];
            #pragma unroll
            for (int np = 0; np < 4; np++) {
                uint32_t r[4];
                ldmatrix_x4(r, smem_u32(kb + (np * 16 + b_ro) * PT + ks * 16 + b_co));
                bb[2*np    ][0] = r[0]; bb[2*np    ][1] = r[1];
                bb[2*np + 1][0] = r[2]; bb[2*np + 1][1] = r[3];
            }
            #pragma unroll
            for (int nt = 0; nt < 8; nt++)
                mma_f16(c_s[nt], a_q[ks], bb[nt]);
        }

        float mx0 = -1e30f, mx1 = -1e30f;
        #pragma unroll
        for (int nt = 0; nt < 8; nt++) {
            const int c0 = nt * 8 + qc * 2;
            c_s[nt][0] = mk[buf * 64 + c0    ] ? c_s[nt][0] * 0.125f : -1e9f;
            c_s[nt][1] = mk[buf * 64 + c0 + 1] ? c_s[nt][1] * 0.125f : -1e9f;
            c_s[nt][2] = mk[buf * 64 + c0    ] ? c_s[nt][2] * 0.125f : -1e9f;
            c_s[nt][3] = mk[buf * 64 + c0 + 1] ? c_s[nt][3] * 0.125f : -1e9f;
            mx0 = fmaxf(mx0, fmaxf(c_s[nt][0], c_s[nt][1]));
            mx1 = fmaxf(mx1, fmaxf(c_s[nt][2], c_s[nt][3]));
        }
        #pragma unroll
        for (int off = 1; off < 4; off <<= 1) {
            mx0 = fmaxf(mx0, __shfl_xor_sync(0xffffffffu, mx0, off));
            mx1 = fmaxf(mx1, __shfl_xor_sync(0xffffffffu, mx1, off));
        }
        const float mn0 = fmaxf(m0r, mx0), mn1 = fmaxf(m1r, mx1);
        const float al0 = __expf(m0r - mn0), al1 = __expf(m1r - mn1);
        float s0 = 0.f, s1 = 0.f;
        #pragma unroll
        for (int nt = 0; nt < 8; nt++) {
            c_s[nt][0] = __expf(c_s[nt][0] - mn0);
            c_s[nt][1] = __expf(c_s[nt][1] - mn0);
            c_s[nt][2] = __expf(c_s[nt][2] - mn1);
            c_s[nt][3] = __expf(c_s[nt][3] - mn1);
            s0 += c_s[nt][0] + c_s[nt][1];
            s1 += c_s[nt][2] + c_s[nt][3];
        }
        #pragma unroll
        for (int off = 1; off < 4; off <<= 1) {
            s0 += __shfl_xor_sync(0xffffffffu, s0, off);
            s1 += __shfl_xor_sync(0xffffffffu, s1, off);
        }
        l0r = l0r * al0 + s0;  m0r = mn0;
        l1r = l1r * al1 + s1;  m1r = mn1;
        #pragma unroll
        for (int nt = 0; nt < 8; nt++) {
            c_o[nt][0] *= al0; c_o[nt][1] *= al0;
            c_o[nt][2] *= al1; c_o[nt][3] *= al1;
        }

        uint32_t ap[4][4];
        #pragma unroll
        for (int ks = 0; ks < 4; ks++) {
            ap[ks][0] = pack_h2(c_s[2*ks    ][0], c_s[2*ks    ][1]);
            ap[ks][1] = pack_h2(c_s[2*ks    ][2], c_s[2*ks    ][3]);
            ap[ks][2] = pack_h2(c_s[2*ks + 1][0], c_s[2*ks + 1][1]);
            ap[ks][3] = pack_h2(c_s[2*ks + 1][2], c_s[2*ks + 1][3]);
        }

        const __half* vb = Vs + buf * T_H;
        #pragma unroll
        for (int ks = 0; ks < 4; ks++) {
            uint32_t bb[8][2];
            #pragma unroll
            for (int np = 0; np < 4; np++) {
                uint32_t r[4];
                ldmatrix_x4(r, smem_u32(vb + (np * 16 + b_ro) * PT + ks * 16 + b_co));
                bb[2*np    ][0] = r[0]; bb[2*np    ][1] = r[1];
                bb[2*np + 1][0] = r[2]; bb[2*np + 1][1] = r[3];
            }
            #pragma unroll
            for (int nt = 0; nt < 8; nt++)
                mma_f16(c_o[nt], ap[ks], bb[nt]);
        }

        if (t + 1 < NT) cp_wait<0>();
        __syncthreads();
    }

    const float i0 = 1.f / l0r, i1 = 1.f / l1r;
    #pragma unroll
    for (int nt = 0; nt < 8; nt++) {
        const size_t r0 = (size_t)(bS + q0 + wm + qr);
        const int col = hoff + nt * 8 + qc * 2;
        *(__half2*)&O[r0 * DM + col] =
            __floats2half2_rn(c_o[nt][0] * i0, c_o[nt][1] * i0);
        *(__half2*)&O[(r0 + 8) * DM + col] =
            __floats2half2_rn(c_o[nt][2] * i1, c_o[nt][3] * i1);
    }
}

// ---------------- launch ---------------------------------------------------
extern "C" void kernel_launch(void* const* d_in, const int* in_sizes, int n_in,
                              void* d_out, int out_size)
{
    const float* x    = (const float*)d_in[0];
    const int*   mask = (const int*)  d_in[1];
    const float* Wq   = (const float*)d_in[2];
    const float* bq   = (const float*)d_in[3];
    const float* Wk   = (const float*)d_in[4];
    const float* bk   = (const float*)d_in[5];
    const float* Wv   = (const float*)d_in[6];
    const float* bv   = (const float*)d_in[7];
    const float* Wo   = (const float*)d_in[8];
    const float* bo   = (const float*)d_in[9];
    const float* W1   = (const float*)d_in[10];
    const float* b1   = (const float*)d_in[11];
    const float* W2   = (const float*)d_in[12];
    const float* b2   = (const float*)d_in[13];
    const float* g1   = (const float*)d_in[14];
    const float* be1  = (const float*)d_in[15];
    const float* g2   = (const float*)d_in[16];
    const float* be2  = (const float*)d_in[17];
    float* out = (float*)d_out;

    __half *h, *q, *k, *vt, *att, *h2, *ff;
    float  *x1;
    __half *wqkvt, *wot, *w1t, *w2t;
    cudaGetSymbolAddress((void**)&h,     g_h);
    cudaGetSymbolAddress((void**)&q,     g_q);
    cudaGetSymbolAddress((void**)&k,     g_k);
    cudaGetSymbolAddress((void**)&vt,    g_vt);
    cudaGetSymbolAddress((void**)&att,   g_att);
    cudaGetSymbolAddress((void**)&x1,    g_x1);
    cudaGetSymbolAddress((void**)&h2,    g_h2);
    cudaGetSymbolAddress((void**)&ff,    g_ff);
    cudaGetSymbolAddress((void**)&wqkvt, g_wqkvt);
    cudaGetSymbolAddress((void**)&wot,   g_wot);
    cudaGetSymbolAddress((void**)&w1t,   g_w1t);
    cudaGetSymbolAddress((void**)&w2t,   g_w2t);

    cudaFuncSetAttribute(attn_kernel,
                         cudaFuncAttributeMaxDynamicSharedMemorySize, ATTN_SMEM);
    cudaFuncSetAttribute(mma_gemm<0, 0>,
                         cudaFuncAttributeMaxDynamicSharedMemorySize, GEMM_SMEM);
    cudaFuncSetAttribute(mma_gemm<0, 1>,
                         cudaFuncAttributeMaxDynamicSharedMemorySize, GEMM_SMEM);
    cudaFuncSetAttribute(mma_gemm<0, 3>,
                         cudaFuncAttributeMaxDynamicSharedMemorySize, GEMM_SMEM);
    cudaFuncSetAttribute(mma_gemm<1, 1>,
                         cudaFuncAttributeMaxDynamicSharedMemorySize, GEMM_SMEM);

    // all 6 weight transposes in one launch
    tr6_kernel<<<12288, 256>>>(Wq, Wk, Wv, Wo, W1, W2, wqkvt, wot, w1t, w2t);

    ln_kernel<<<NTOK, 256>>>(x, g1, be1, h);
    // fused Q/K/V projection (writes g_q, g_k, g_vt directly)
    mma_gemm<0, 3><<<dim3(3 * DM / 128, NTOK / 128), 256, GEMM_SMEM>>>(
        h, wqkvt, bq, bk, bv, nullptr, nullptr, DM, 3 * DM);
    attn_kernel<<<dim3(SEQ / 64, NH, NB), 128, ATTN_SMEM>>>(q, k, vt, mask, att);
    mma_gemm<0, 0><<<dim3(DM / 128, NTOK / 128), 256, GEMM_SMEM>>>(
        att, wot, bo, nullptr, nullptr, x, x1, DM, DM);
    ln_kernel<<<NTOK, 256>>>(x1, g2, be2, h2);
    mma_gemm<1, 1><<<dim3(DFF / 128, NTOK / 128), 256, GEMM_SMEM>>>(
        h2, w1t, b1, nullptr, nullptr, nullptr, ff, DM, DFF);
    mma_gemm<0, 0><<<dim3(DM / 128, NTOK / 128), 256, GEMM_SMEM>>>(
        ff, w2t, b2, nullptr, nullptr, x1, out, DFF, DM);
}

// round 15
// speedup vs baseline: 1.1240x; 1.0062x over previous
#include <cuda_runtime.h>
#include <cuda_fp16.h>
#include <math.h>
#include <stdint.h>

#define NTOK 8192
#define DM   1024
#define DFF  4096
#define SEQ  2048
#define NB   4
#define NH   16
#define DKH  64

// 0.125 (1/sqrt(dk)) * log2(e): folded into Q projection; attention uses ex2.
#define QSCL 0.18033688011112042f

// ---------------- scratch (device globals: allocation-guard safe) ----------
__device__ __half g_h  [(size_t)NTOK * DM];
__device__ __half g_q  [(size_t)NTOK * DM];
__device__ __half g_k  [(size_t)NTOK * DM];
__device__ __half g_vt [(size_t)NB * DM * SEQ];   // V transposed: [b][col][s]
__device__ __half g_att[(size_t)NTOK * DM];
__device__ float  g_x1 [(size_t)NTOK * DM];
__device__ __half g_h2 [(size_t)NTOK * DM];
__device__ __half g_ff [(size_t)NTOK * DFF];
__device__ __half g_wqkvt[(size_t)3 * DM * DM];   // concat W{q,k,v}^T
__device__ __half g_wot[(size_t)DM * DM];
__device__ __half g_w1t[(size_t)DFF * DM];
__device__ __half g_w2t[(size_t)DM * DFF];

// ---------------- helpers ---------------------------------------------------
__device__ __forceinline__ uint32_t smem_u32(const void* p) {
    uint32_t a;
    asm("{ .reg .u64 t; cvta.to.shared.u64 t, %1; cvt.u32.u64 %0, t; }"
        : "=r"(a) : "l"(p));
    return a;
}
__device__ __forceinline__ void cp_async16(uint32_t dst, const void* src) {
    asm volatile("cp.async.cg.shared.global [%0], [%1], 16;" :: "r"(dst), "l"(src));
}
__device__ __forceinline__ void cp_commit() {
    asm volatile("cp.async.commit_group;" ::: "memory");
}
template <int N>
__device__ __forceinline__ void cp_wait() {
    asm volatile("cp.async.wait_group %0;" :: "n"(N) : "memory");
}
__device__ __forceinline__ void ldmatrix_x4(uint32_t* r, uint32_t addr) {
    asm volatile("ldmatrix.sync.aligned.m8n8.x4.shared.b16 {%0,%1,%2,%3}, [%4];"
                 : "=r"(r[0]), "=r"(r[1]), "=r"(r[2]), "=r"(r[3]) : "r"(addr));
}
__device__ __forceinline__ void mma_f16(float* c, const uint32_t* a, const uint32_t* b) {
    asm volatile(
        "mma.sync.aligned.m16n8k16.row.col.f32.f16.f16.f32 "
        "{%0,%1,%2,%3}, {%4,%5,%6,%7}, {%8,%9}, {%0,%1,%2,%3};"
        : "+f"(c[0]), "+f"(c[1]), "+f"(c[2]), "+f"(c[3])
        : "r"(a[0]), "r"(a[1]), "r"(a[2]), "r"(a[3]), "r"(b[0]), "r"(b[1]));
}
__device__ __forceinline__ uint32_t pack_h2(float lo, float hi) {
    __half2 h = __floats2half2_rn(lo, hi);
    return *(uint32_t*)&h;
}
__device__ __forceinline__ float ex2f(float x) {
    float y;
    asm("ex2.approx.ftz.f32 %0, %1;" : "=f"(y) : "f"(x));
    return y;
}
__device__ __forceinline__ float gelu_exact(float v)
{
    return 0.5f * v * (1.0f + erff(v * 0.70710678118654752f));
}

// ---------------- merged weight transpose (6 jobs, 1 launch) ---------------
__global__ void __launch_bounds__(256)
tr6_kernel(const float* __restrict__ Wq, const float* __restrict__ Wk,
           const float* __restrict__ Wv, const float* __restrict__ Wo,
           const float* __restrict__ W1, const float* __restrict__ W2,
           __half* __restrict__ wqkvt, __half* __restrict__ wot,
           __half* __restrict__ w1t,   __half* __restrict__ w2t)
{
    const int id = blockIdx.x;
    int job, base;
    if (id < 4096)      { job = id >> 10; base = id & 1023; }
    else if (id < 8192) { job = 4; base = id - 4096; }
    else                { job = 5; base = id - 8192; }

    const float* in; __half* out; int rows, cols, gx;
    switch (job) {
        case 0: in = Wq; out = wqkvt;                       rows = DM;  cols = DM;  gx = 32;  break;
        case 1: in = Wk; out = wqkvt + (size_t)DM * DM;     rows = DM;  cols = DM;  gx = 32;  break;
        case 2: in = Wv; out = wqkvt + (size_t)2 * DM * DM; rows = DM;  cols = DM;  gx = 32;  break;
        case 3: in = Wo; out = wot;                         rows = DM;  cols = DM;  gx = 32;  break;
        case 4: in = W1; out = w1t;                         rows = DM;  cols = DFF; gx = 128; break;
        default:in = W2; out = w2t;                         rows = DFF; cols = DM;  gx = 32;  break;
    }
    const int bx = base % gx, by = base / gx;

    __shared__ float t[32][33];
    const int tx = threadIdx.x & 31, ty = threadIdx.x >> 5;
    const int x  = bx * 32 + tx;
    const int y0 = by * 32;
    #pragma unroll
    for (int j = ty; j < 32; j += 8)
        t[j][tx] = in[(size_t)(y0 + j) * cols + x];
    __syncthreads();
    const int ox  = y0 + tx;
    const int oy0 = bx * 32;
    #pragma unroll
    for (int j = ty; j < 32; j += 8)
        out[(size_t)(oy0 + j) * rows + ox] = __float2half_rn(t[tx][j]);
}

// ---------------- LayerNorm (fp32 in -> fp16 out; only feeds GEMMs) --------
__global__ void __launch_bounds__(256)
ln_kernel(const float* __restrict__ x, const float* __restrict__ gam,
          const float* __restrict__ bet, __half* __restrict__ out)
{
    const int row = blockIdx.x;
    const float4 v = ((const float4*)(x + (size_t)row * DM))[threadIdx.x];
    float s = v.x + v.y + v.z + v.w;
    float q = v.x*v.x + v.y*v.y + v.z*v.z + v.w*v.w;
    #pragma unroll
    for (int o = 16; o; o >>= 1) {
        s += __shfl_xor_sync(0xffffffffu, s, o);
        q += __shfl_xor_sync(0xffffffffu, q, o);
    }
    __shared__ float ss[8], sq[8];
    const int w = threadIdx.x >> 5, l = threadIdx.x & 31;
    if (l == 0) { ss[w] = s; sq[w] = q; }
    __syncthreads();
    if (w == 0) {
        s = (l < 8) ? ss[l] : 0.f;
        q = (l < 8) ? sq[l] : 0.f;
        #pragma unroll
        for (int o = 4; o; o >>= 1) {
            s += __shfl_xor_sync(0xffffffffu, s, o);
            q += __shfl_xor_sync(0xffffffffu, q, o);
        }
        if (l == 0) { ss[0] = s; sq[0] = q; }
    }
    __syncthreads();
    const float mean = ss[0] * (1.f / DM);
    const float var  = sq[0] * (1.f / DM) - mean * mean;
    const float rstd = rsqrtf(var + 1e-5f);
    const float4 g4 = ((const float4*)gam)[threadIdx.x];
    const float4 b4 = ((const float4*)bet)[threadIdx.x];
    __half2* o2 = (__half2*)(out + (size_t)row * DM);
    o2[threadIdx.x * 2    ] = __floats2half2_rn((v.x - mean) * rstd * g4.x + b4.x,
                                                (v.y - mean) * rstd * g4.y + b4.y);
    o2[threadIdx.x * 2 + 1] = __floats2half2_rn((v.z - mean) * rstd * g4.z + b4.z,
                                                (v.w - mean) * rstd * g4.w + b4.w);
}

// ---------------- fp16 mma GEMM (4-stage cp.async + ldmatrix) --------------
// 8 warps, warp tile 64x32. CTA tile 128x128, K-chunk 32 (R14 best config).
// OUT: 0 = fp32 (+residual), 1 = fp16, 3 = fused QKV (writes g_q/g_k/g_vt;
//      q output is pre-scaled by QSCL for the log2-domain softmax)
#define PH 40
#define STG_H (128 * PH)
#define NSTG 4
#define GEMM_SMEM (NSTG * 2 * STG_H * 2)

template <int ACT, int OUT>
__global__ void __launch_bounds__(256, 2)
mma_gemm(const __half* __restrict__ A, const __half* __restrict__ Bt,
         const float* __restrict__ bias, const float* __restrict__ bias2,
         const float* __restrict__ bias3, const float* __restrict__ R,
         void* __restrict__ Cout, int K, int Mout)
{
    extern __shared__ __half hsm[];
    __half* Asm = hsm;
    __half* Bsm = hsm + NSTG * STG_H;

    const int tid  = threadIdx.x;
    const int lane = tid & 31, wid = tid >> 5;
    const int wm = (wid >> 2) * 64;
    const int wn = (wid & 3) * 32;
    const int qr = lane >> 2, qc = lane & 3;
    const int lm8 = lane >> 3;
    const int l8  = lane & 7;
    const int m0 = blockIdx.y * 128, n0 = blockIdx.x * 128;

    float c[4][4][4];
    #pragma unroll
    for (int i = 0; i < 4; i++)
        #pragma unroll
        for (int j = 0; j < 4; j++)
            #pragma unroll
            for (int e = 0; e < 4; e++) c[i][j][e] = 0.f;

    const int lrow = tid >> 1;
    const int lseg = (tid & 1) * 16;
    const __half* Ap = A  + (size_t)(m0 + lrow) * K + lseg;
    const __half* Bp = Bt + (size_t)(n0 + lrow) * K + lseg;

    const int NCH = K >> 5;

    auto load_stage = [&](int st, int ch) {
        const int koff = ch * 32;
        __half* as = Asm + st * STG_H + lrow * PH + lseg;
        __half* bs = Bsm + st * STG_H + lrow * PH + lseg;
        cp_async16(smem_u32(as),     Ap + koff);
        cp_async16(smem_u32(as + 8), Ap + koff + 8);
        cp_async16(smem_u32(bs),     Bp + koff);
        cp_async16(smem_u32(bs + 8), Bp + koff + 8);
        cp_commit();
    };

    load_stage(0, 0);
    load_stage(1, 1);
    load_stage(2, 2);

    const int a_ro = ((lm8 & 1) << 3) + l8;
    const int a_co = (lm8 >> 1) << 3;
    const int b_ro = ((lm8 >> 1) << 3) + l8;
    const int b_co = (lm8 & 1) << 3;

    for (int ch = 0; ch < NCH; ch++) {
        const int buf = ch % NSTG;
        cp_wait<2>();
        __syncthreads();

        if (ch + 3 < NCH) load_stage((ch + 3) % NSTG, ch + 3);
        else              cp_commit();

        const __half* as = Asm + buf * STG_H;
        const __half* bs = Bsm + buf * STG_H;

        #pragma unroll
        for (int ks = 0; ks < 2; ks++) {
            uint32_t a[4][4], b[4][2];
            #pragma unroll
            for (int mt = 0; mt < 4; mt++)
                ldmatrix_x4(a[mt],
                    smem_u32(as + (wm + mt * 16 + a_ro) * PH + ks * 16 + a_co));
            #pragma unroll
            for (int np = 0; np < 2; np++) {
                uint32_t r[4];
                ldmatrix_x4(r,
                    smem_u32(bs + (wn + np * 16 + b_ro) * PH + ks * 16 + b_co));
                b[2*np    ][0] = r[0]; b[2*np    ][1] = r[1];
                b[2*np + 1][0] = r[2]; b[2*np + 1][1] = r[3];
            }
            #pragma unroll
            for (int mt = 0; mt < 4; mt++)
                #pragma unroll
                for (int nt = 0; nt < 4; nt++)
                    mma_f16(c[mt][nt], a[mt], b[nt]);
        }
    }

    // ---- epilogue ----
    if (OUT == 3) {
        const int seg   = n0 >> 10;
        const int nbase = (n0 & 1023) + wn;
        const float* bp = (seg == 0) ? bias : (seg == 1 ? bias2 : bias3);
        #pragma unroll
        for (int mt = 0; mt < 4; mt++) {
            #pragma unroll
            for (int half_ = 0; half_ < 2; half_++) {
                const int gm = m0 + wm + mt * 16 + qr + half_ * 8;
                #pragma unroll
                for (int nt = 0; nt < 4; nt++) {
                    const int col = nbase + nt * 8 + qc * 2;
                    float v0 = c[mt][nt][half_ * 2 + 0] + bp[col];
                    float v1 = c[mt][nt][half_ * 2 + 1] + bp[col + 1];
                    if (seg == 0) {
                        v0 *= QSCL; v1 *= QSCL;   // fold softmax scale+log2e into q
                        *(__half2*)&g_q[(size_t)gm * DM + col] = __floats2half2_rn(v0, v1);
                    } else if (seg == 1) {
                        *(__half2*)&g_k[(size_t)gm * DM + col] = __floats2half2_rn(v0, v1);
                    } else {
                        const int bb = gm >> 11, s = gm & 2047;
                        g_vt[((size_t)bb * DM + col    ) * SEQ + s] = __float2half_rn(v0);
                        g_vt[((size_t)bb * DM + col + 1) * SEQ + s] = __float2half_rn(v1);
                    }
                }
            }
        }
    } else {
        #pragma unroll
        for (int mt = 0; mt < 4; mt++) {
            #pragma unroll
            for (int half_ = 0; half_ < 2; half_++) {
                const int gm = m0 + wm + mt * 16 + qr + half_ * 8;
                #pragma unroll
                for (int nt = 0; nt < 4; nt++) {
                    const int col = n0 + wn + nt * 8 + qc * 2;
                    float v0 = c[mt][nt][half_ * 2 + 0] + bias[col];
                    float v1 = c[mt][nt][half_ * 2 + 1] + bias[col + 1];
                    if (ACT == 1) { v0 = gelu_exact(v0); v1 = gelu_exact(v1); }
                    if (OUT == 0) {
                        const float2 rv = *(const float2*)&R[(size_t)gm * Mout + col];
                        *(float2*)((float*)Cout + (size_t)gm * Mout + col) =
                            make_float2(v0 + rv.x, v1 + rv.y);
                    } else {
                        *(__half2*)((__half*)Cout + (size_t)gm * Mout + col) =
                            __floats2half2_rn(v0, v1);
                    }
                }
            }
        }
    }
}

// ---------------- fp16 mma flash attention (log2-domain softmax) -----------
#define PT 72
#define T_H (64 * PT)
// halves: Qs + 2*Ks + 2*Vs; ints: 2*64 mask; floats: 2*64 bias
#define ATTN_SMEM ((T_H + 2 * T_H + 2 * T_H) * 2 + 2 * 64 * 4 + 2 * 64 * 4)

__global__ void __launch_bounds__(128)
attn_kernel(const __half* __restrict__ Q, const __half* __restrict__ K,
            const __half* __restrict__ Vt, const int* __restrict__ mask,
            __half* __restrict__ O)
{
    extern __shared__ __half asm_[];
    __half* Qs = asm_;
    __half* Ks = asm_ + T_H;
    __half* Vs = asm_ + 3 * T_H;
    int*    mk = (int*)(asm_ + 5 * T_H);
    float*  mb = (float*)(mk + 2 * 64);

    const int tid  = threadIdx.x;
    const int lane = tid & 31, wid = tid >> 5;
    const int qr = lane >> 2, qc = lane & 3;
    const int lm8 = lane >> 3, l8 = lane & 7;
    const int wm = wid * 16;
    const int b  = blockIdx.z, hh = blockIdx.y;
    const int q0 = blockIdx.x * 64;
    const int bS = b * SEQ;
    const int hoff = hh * DKH;

    const int lrow = tid >> 1;
    const int lseg = (tid & 1) * 32;

    {
        const __half* src = Q + (size_t)(bS + q0 + lrow) * DM + hoff + lseg;
        uint32_t dst = smem_u32(Qs + lrow * PT + lseg);
        #pragma unroll
        for (int u = 0; u < 4; u++) cp_async16(dst + u * 16, src + u * 8);
        cp_commit();
    }

    const __half* VtBase = Vt + ((size_t)b * DM + hoff) * SEQ;

    auto load_kv = [&](int buf, int kv0) {
        const __half* ks = K + (size_t)(bS + kv0 + lrow) * DM + hoff + lseg;
        const __half* vs = VtBase + (size_t)lrow * SEQ + kv0 + lseg;
        uint32_t dk = smem_u32(Ks + buf * T_H + lrow * PT + lseg);
        uint32_t dv = smem_u32(Vs + buf * T_H + lrow * PT + lseg);
        #pragma unroll
        for (int u = 0; u < 4; u++) {
            cp_async16(dk + u * 16, ks + u * 8);
            cp_async16(dv + u * 16, vs + u * 8);
        }
        if (tid < 16)
            cp_async16(smem_u32(mk + buf * 64 + tid * 4), mask + bS + kv0 + tid * 4);
    };

    load_kv(0, 0);
    cp_commit();
    cp_wait<0>();
    if (tid < 64) mb[tid] = mk[tid] ? 0.f : -1e9f;
    __syncthreads();

    const int a_ro = ((lm8 & 1) << 3) + l8;
    const int a_co = (lm8 >> 1) << 3;
    const int b_ro = ((lm8 >> 1) << 3) + l8;
    const int b_co = (lm8 & 1) << 3;

    uint32_t a_q[4][4];
    #pragma unroll
    for (int ks = 0; ks < 4; ks++)
        ldmatrix_x4(a_q[ks], smem_u32(Qs + (wm + a_ro) * PT + ks * 16 + a_co));

    float c_o[8][4];
    #pragma unroll
    for (int nt = 0; nt < 8; nt++)
        #pragma unroll
        for (int e = 0; e < 4; e++) c_o[nt][e] = 0.f;
    float m0r = -1e30f, m1r = -1e30f, l0r = 0.f, l1r = 0.f;

    const int NT = SEQ / 64;
    for (int t = 0; t < NT; t++) {
        const int buf = t & 1;
        if (t + 1 < NT) { load_kv(buf ^ 1, (t + 1) * 64); cp_commit(); }

        // ---- S = Q K^T (log2 domain: q pre-scaled by 0.125*log2e) ----
        float c_s[8][4];
        #pragma unroll
        for (int nt = 0; nt < 8; nt++)
            #pragma unroll
            for (int e = 0; e < 4; e++) c_s[nt][e] = 0.f;

        const __half* kb = Ks + buf * T_H;
        #pragma unroll
        for (int ks = 0; ks < 4; ks++) {
            uint32_t bb[8][2];
            #pragma unroll
            for (int np = 0; np < 4; np++) {
                uint32_t r[4];
                ldmatrix_x4(r, smem_u32(kb + (np * 16 + b_ro) * PT + ks * 16 + b_co));
                bb[2*np    ][0] = r[0]; bb[2*np    ][1] = r[1];
                bb[2*np + 1][0] = r[2]; bb[2*np + 1][1] = r[3];
            }
            #pragma unroll
            for (int nt = 0; nt < 8; nt++)
                mma_f16(c_s[nt], a_q[ks], bb[nt]);
        }

        // ---- mask (additive) + online softmax (base-2) ----
        float mx0 = -1e30f, mx1 = -1e30f;
        #pragma unroll
        for (int nt = 0; nt < 8; nt++) {
            const int c0 = nt * 8 + qc * 2;
            const float b0 = mb[buf * 64 + c0], b1 = mb[buf * 64 + c0 + 1];
            c_s[nt][0] += b0; c_s[nt][1] += b1;
            c_s[nt][2] += b0; c_s[nt][3] += b1;
            mx0 = fmaxf(mx0, fmaxf(c_s[nt][0], c_s[nt][1]));
            mx1 = fmaxf(mx1, fmaxf(c_s[nt][2], c_s[nt][3]));
        }
        #pragma unroll
        for (int off = 1; off < 4; off <<= 1) {
            mx0 = fmaxf(mx0, __shfl_xor_sync(0xffffffffu, mx0, off));
            mx1 = fmaxf(mx1, __shfl_xor_sync(0xffffffffu, mx1, off));
        }
        const float mn0 = fmaxf(m0r, mx0), mn1 = fmaxf(m1r, mx1);
        const float al0 = ex2f(m0r - mn0), al1 = ex2f(m1r - mn1);
        float s0 = 0.f, s1 = 0.f;
        #pragma unroll
        for (int nt = 0; nt < 8; nt++) {
            c_s[nt][0] = ex2f(c_s[nt][0] - mn0);
            c_s[nt][1] = ex2f(c_s[nt][1] - mn0);
            c_s[nt][2] = ex2f(c_s[nt][2] - mn1);
            c_s[nt][3] = ex2f(c_s[nt][3] - mn1);
            s0 += c_s[nt][0] + c_s[nt][1];
            s1 += c_s[nt][2] + c_s[nt][3];
        }
        #pragma unroll
        for (int off = 1; off < 4; off <<= 1) {
            s0 += __shfl_xor_sync(0xffffffffu, s0, off);
            s1 += __shfl_xor_sync(0xffffffffu, s1, off);
        }
        l0r = l0r * al0 + s0;  m0r = mn0;
        l1r = l1r * al1 + s1;  m1r = mn1;
        #pragma unroll
        for (int nt = 0; nt < 8; nt++) {
            c_o[nt][0] *= al0; c_o[nt][1] *= al0;
            c_o[nt][2] *= al1; c_o[nt][3] *= al1;
        }

        uint32_t ap[4][4];
        #pragma unroll
        for (int ks = 0; ks < 4; ks++) {
            ap[ks][0] = pack_h2(c_s[2*ks    ][0], c_s[2*ks    ][1]);
            ap[ks][1] = pack_h2(c_s[2*ks    ][2], c_s[2*ks    ][3]);
            ap[ks][2] = pack_h2(c_s[2*ks + 1][0], c_s[2*ks + 1][1]);
            ap[ks][3] = pack_h2(c_s[2*ks + 1][2], c_s[2*ks + 1][3]);
        }

        const __half* vb = Vs + buf * T_H;
        #pragma unroll
        for (int ks = 0; ks < 4; ks++) {
            uint32_t bb[8][2];
            #pragma unroll
            for (int np = 0; np < 4; np++) {
                uint32_t r[4];
                ldmatrix_x4(r, smem_u32(vb + (np * 16 + b_ro) * PT + ks * 16 + b_co));
                bb[2*np    ][0] = r[0]; bb[2*np    ][1] = r[1];
                bb[2*np + 1][0] = r[2]; bb[2*np + 1][1] = r[3];
            }
            #pragma unroll
            for (int nt = 0; nt < 8; nt++)
                mma_f16(c_o[nt], ap[ks], bb[nt]);
        }

        if (t + 1 < NT) {
            cp_wait<0>();
            if (tid < 64)
                mb[(buf ^ 1) * 64 + tid] = mk[(buf ^ 1) * 64 + tid] ? 0.f : -1e9f;
        }
        __syncthreads();
    }

    const float i0 = 1.f / l0r, i1 = 1.f / l1r;
    #pragma unroll
    for (int nt = 0; nt < 8; nt++) {
        const size_t r0 = (size_t)(bS + q0 + wm + qr);
        const int col = hoff + nt * 8 + qc * 2;
        *(__half2*)&O[r0 * DM + col] =
            __floats2half2_rn(c_o[nt][0] * i0, c_o[nt][1] * i0);
        *(__half2*)&O[(r0 + 8) * DM + col] =
            __floats2half2_rn(c_o[nt][2] * i1, c_o[nt][3] * i1);
    }
}

// ---------------- launch ---------------------------------------------------
extern "C" void kernel_launch(void* const* d_in, const int* in_sizes, int n_in,
                              void* d_out, int out_size)
{
    const float* x    = (const float*)d_in[0];
    const int*   mask = (const int*)  d_in[1];
    const float* Wq   = (const float*)d_in[2];
    const float* bq   = (const float*)d_in[3];
    const float* Wk   = (const float*)d_in[4];
    const float* bk   = (const float*)d_in[5];
    const float* Wv   = (const float*)d_in[6];
    const float* bv   = (const float*)d_in[7];
    const float* Wo   = (const float*)d_in[8];
    const float* bo   = (const float*)d_in[9];
    const float* W1   = (const float*)d_in[10];
    const float* b1   = (const float*)d_in[11];
    const float* W2   = (const float*)d_in[12];
    const float* b2   = (const float*)d_in[13];
    const float* g1   = (const float*)d_in[14];
    const float* be1  = (const float*)d_in[15];
    const float* g2   = (const float*)d_in[16];
    const float* be2  = (const float*)d_in[17];
    float* out = (float*)d_out;

    __half *h, *q, *k, *vt, *att, *h2, *ff;
    float  *x1;
    __half *wqkvt, *wot, *w1t, *w2t;
    cudaGetSymbolAddress((void**)&h,     g_h);
    cudaGetSymbolAddress((void**)&q,     g_q);
    cudaGetSymbolAddress((void**)&k,     g_k);
    cudaGetSymbolAddress((void**)&vt,    g_vt);
    cudaGetSymbolAddress((void**)&att,   g_att);
    cudaGetSymbolAddress((void**)&x1,    g_x1);
    cudaGetSymbolAddress((void**)&h2,    g_h2);
    cudaGetSymbolAddress((void**)&ff,    g_ff);
    cudaGetSymbolAddress((void**)&wqkvt, g_wqkvt);
    cudaGetSymbolAddress((void**)&wot,   g_wot);
    cudaGetSymbolAddress((void**)&w1t,   g_w1t);
    cudaGetSymbolAddress((void**)&w2t,   g_w2t);

    cudaFuncSetAttribute(attn_kernel,
                         cudaFuncAttributeMaxDynamicSharedMemorySize, ATTN_SMEM);
    cudaFuncSetAttribute(mma_gemm<0, 0>,
                         cudaFuncAttributeMaxDynamicSharedMemorySize, GEMM_SMEM);
    cudaFuncSetAttribute(mma_gemm<0, 1>,
                         cudaFuncAttributeMaxDynamicSharedMemorySize, GEMM_SMEM);
    cudaFuncSetAttribute(mma_gemm<0, 3>,
                         cudaFuncAttributeMaxDynamicSharedMemorySize, GEMM_SMEM);
    cudaFuncSetAttribute(mma_gemm<1, 1>,
                         cudaFuncAttributeMaxDynamicSharedMemorySize, GEMM_SMEM);

    tr6_kernel<<<12288, 256>>>(Wq, Wk, Wv, Wo, W1, W2, wqkvt, wot, w1t, w2t);

    ln_kernel<<<NTOK, 256>>>(x, g1, be1, h);
    mma_gemm<0, 3><<<dim3(3 * DM / 128, NTOK / 128), 256, GEMM_SMEM>>>(
        h, wqkvt, bq, bk, bv, nullptr, nullptr, DM, 3 * DM);
    attn_kernel<<<dim3(SEQ / 64, NH, NB), 128, ATTN_SMEM>>>(q, k, vt, mask, att);
    mma_gemm<0, 0><<<dim3(DM / 128, NTOK / 128), 256, GEMM_SMEM>>>(
        att, wot, bo, nullptr, nullptr, x, x1, DM, DM);
    ln_kernel<<<NTOK, 256>>>(x1, g2, be2, h2);
    mma_gemm<1, 1><<<dim3(DFF / 128, NTOK / 128), 256, GEMM_SMEM>>>(
        h2, w1t, b1, nullptr, nullptr, nullptr, ff, DM, DFF);
    mma_gemm<0, 0><<<dim3(DM / 128, NTOK / 128), 256, GEMM_SMEM>>>(
        ff, w2t, b2, nullptr, nullptr, x1, out, DFF, DM);
}

// round 16
// speedup vs baseline: 1.2096x; 1.0762x over previous
#include <cuda_runtime.h>
#include <cuda_fp16.h>
#include <math.h>
#include <stdint.h>

#define NTOK 8192
#define DM   1024
#define DFF  4096
#define SEQ  2048
#define NB   4
#define NH   16
#define DKH  64

// 0.125 (1/sqrt(dk)) * log2(e): folded into Q projection; attention uses ex2.
#define QSCL 0.18033688011112042f

// ---------------- scratch (device globals: allocation-guard safe) ----------
__device__ __half g_h  [(size_t)NTOK * DM];
__device__ __half g_q  [(size_t)NTOK * DM];
__device__ __half g_k  [(size_t)NTOK * DM];
__device__ __half g_vt [(size_t)NB * DM * SEQ];   // V transposed: [b][col][s]
__device__ __half g_att[(size_t)NTOK * DM];
__device__ float  g_x1 [(size_t)NTOK * DM];
__device__ __half g_h2 [(size_t)NTOK * DM];
__device__ __half g_ff [(size_t)NTOK * DFF];
__device__ __half g_wqkvt[(size_t)3 * DM * DM];   // concat W{q,k,v}^T
__device__ __half g_wot[(size_t)DM * DM];
__device__ __half g_w1t[(size_t)DFF * DM];
__device__ __half g_w2t[(size_t)DM * DFF];

// ---------------- helpers ---------------------------------------------------
__device__ __forceinline__ uint32_t smem_u32(const void* p) {
    uint32_t a;
    asm("{ .reg .u64 t; cvta.to.shared.u64 t, %1; cvt.u32.u64 %0, t; }"
        : "=r"(a) : "l"(p));
    return a;
}
__device__ __forceinline__ void cp_async16(uint32_t dst, const void* src) {
    asm volatile("cp.async.cg.shared.global [%0], [%1], 16;" :: "r"(dst), "l"(src));
}
__device__ __forceinline__ void cp_commit() {
    asm volatile("cp.async.commit_group;" ::: "memory");
}
template <int N>
__device__ __forceinline__ void cp_wait() {
    asm volatile("cp.async.wait_group %0;" :: "n"(N) : "memory");
}
__device__ __forceinline__ void ldmatrix_x4(uint32_t* r, uint32_t addr) {
    asm volatile("ldmatrix.sync.aligned.m8n8.x4.shared.b16 {%0,%1,%2,%3}, [%4];"
                 : "=r"(r[0]), "=r"(r[1]), "=r"(r[2]), "=r"(r[3]) : "r"(addr));
}
__device__ __forceinline__ void mma_f16(float* c, const uint32_t* a, const uint32_t* b) {
    asm volatile(
        "mma.sync.aligned.m16n8k16.row.col.f32.f16.f16.f32 "
        "{%0,%1,%2,%3}, {%4,%5,%6,%7}, {%8,%9}, {%0,%1,%2,%3};"
        : "+f"(c[0]), "+f"(c[1]), "+f"(c[2]), "+f"(c[3])
        : "r"(a[0]), "r"(a[1]), "r"(a[2]), "r"(a[3]), "r"(b[0]), "r"(b[1]));
}
__device__ __forceinline__ uint32_t pack_h2(float lo, float hi) {
    __half2 h = __floats2half2_rn(lo, hi);
    return *(uint32_t*)&h;
}
__device__ __forceinline__ float ex2f(float x) {
    float y;
    asm("ex2.approx.ftz.f32 %0, %1;" : "=f"(y) : "f"(x));
    return y;
}
__device__ __forceinline__ float gelu_exact(float v)
{
    return 0.5f * v * (1.0f + erff(v * 0.70710678118654752f));
}

// ---------------- merged weight transpose (6 jobs, 1 launch) ---------------
__global__ void __launch_bounds__(256)
tr6_kernel(const float* __restrict__ Wq, const float* __restrict__ Wk,
           const float* __restrict__ Wv, const float* __restrict__ Wo,
           const float* __restrict__ W1, const float* __restrict__ W2,
           __half* __restrict__ wqkvt, __half* __restrict__ wot,
           __half* __restrict__ w1t,   __half* __restrict__ w2t)
{
    const int id = blockIdx.x;
    int job, base;
    if (id < 4096)      { job = id >> 10; base = id & 1023; }
    else if (id < 8192) { job = 4; base = id - 4096; }
    else                { job = 5; base = id - 8192; }

    const float* in; __half* out; int rows, cols, gx;
    switch (job) {
        case 0: in = Wq; out = wqkvt;                       rows = DM;  cols = DM;  gx = 32;  break;
        case 1: in = Wk; out = wqkvt + (size_t)DM * DM;     rows = DM;  cols = DM;  gx = 32;  break;
        case 2: in = Wv; out = wqkvt + (size_t)2 * DM * DM; rows = DM;  cols = DM;  gx = 32;  break;
        case 3: in = Wo; out = wot;                         rows = DM;  cols = DM;  gx = 32;  break;
        case 4: in = W1; out = w1t;                         rows = DM;  cols = DFF; gx = 128; break;
        default:in = W2; out = w2t;                         rows = DFF; cols = DM;  gx = 32;  break;
    }
    const int bx = base % gx, by = base / gx;

    __shared__ float t[32][33];
    const int tx = threadIdx.x & 31, ty = threadIdx.x >> 5;
    const int x  = bx * 32 + tx;
    const int y0 = by * 32;
    #pragma unroll
    for (int j = ty; j < 32; j += 8)
        t[j][tx] = in[(size_t)(y0 + j) * cols + x];
    __syncthreads();
    const int ox  = y0 + tx;
    const int oy0 = bx * 32;
    #pragma unroll
    for (int j = ty; j < 32; j += 8)
        out[(size_t)(oy0 + j) * rows + ox] = __float2half_rn(t[tx][j]);
}

// ---------------- LayerNorm (fp32 in -> fp16 out; only feeds GEMMs) --------
__global__ void __launch_bounds__(256)
ln_kernel(const float* __restrict__ x, const float* __restrict__ gam,
          const float* __restrict__ bet, __half* __restrict__ out)
{
    const int row = blockIdx.x;
    const float4 v = ((const float4*)(x + (size_t)row * DM))[threadIdx.x];
    float s = v.x + v.y + v.z + v.w;
    float q = v.x*v.x + v.y*v.y + v.z*v.z + v.w*v.w;
    #pragma unroll
    for (int o = 16; o; o >>= 1) {
        s += __shfl_xor_sync(0xffffffffu, s, o);
        q += __shfl_xor_sync(0xffffffffu, q, o);
    }
    __shared__ float ss[8], sq[8];
    const int w = threadIdx.x >> 5, l = threadIdx.x & 31;
    if (l == 0) { ss[w] = s; sq[w] = q; }
    __syncthreads();
    if (w == 0) {
        s = (l < 8) ? ss[l] : 0.f;
        q = (l < 8) ? sq[l] : 0.f;
        #pragma unroll
        for (int o = 4; o; o >>= 1) {
            s += __shfl_xor_sync(0xffffffffu, s, o);
            q += __shfl_xor_sync(0xffffffffu, q, o);
        }
        if (l == 0) { ss[0] = s; sq[0] = q; }
    }
    __syncthreads();
    const float mean = ss[0] * (1.f / DM);
    const float var  = sq[0] * (1.f / DM) - mean * mean;
    const float rstd = rsqrtf(var + 1e-5f);
    const float4 g4 = ((const float4*)gam)[threadIdx.x];
    const float4 b4 = ((const float4*)bet)[threadIdx.x];
    __half2* o2 = (__half2*)(out + (size_t)row * DM);
    o2[threadIdx.x * 2    ] = __floats2half2_rn((v.x - mean) * rstd * g4.x + b4.x,
                                                (v.y - mean) * rstd * g4.y + b4.y);
    o2[threadIdx.x * 2 + 1] = __floats2half2_rn((v.z - mean) * rstd * g4.z + b4.z,
                                                (v.w - mean) * rstd * g4.w + b4.w);
}

// ---------------- fp16 mma GEMM (4-stage cp.async + ldmatrix) --------------
#define PH 40
#define STG_H (128 * PH)
#define NSTG 4
#define GEMM_SMEM (NSTG * 2 * STG_H * 2)

template <int ACT, int OUT>
__global__ void __launch_bounds__(256, 2)
mma_gemm(const __half* __restrict__ A, const __half* __restrict__ Bt,
         const float* __restrict__ bias, const float* __restrict__ bias2,
         const float* __restrict__ bias3, const float* __restrict__ R,
         void* __restrict__ Cout, int K, int Mout)
{
    extern __shared__ __half hsm[];
    __half* Asm = hsm;
    __half* Bsm = hsm + NSTG * STG_H;

    const int tid  = threadIdx.x;
    const int lane = tid & 31, wid = tid >> 5;
    const int wm = (wid >> 2) * 64;
    const int wn = (wid & 3) * 32;
    const int qr = lane >> 2, qc = lane & 3;
    const int lm8 = lane >> 3;
    const int l8  = lane & 7;
    const int m0 = blockIdx.y * 128, n0 = blockIdx.x * 128;

    float c[4][4][4];
    #pragma unroll
    for (int i = 0; i < 4; i++)
        #pragma unroll
        for (int j = 0; j < 4; j++)
            #pragma unroll
            for (int e = 0; e < 4; e++) c[i][j][e] = 0.f;

    const int lrow = tid >> 1;
    const int lseg = (tid & 1) * 16;
    const __half* Ap = A  + (size_t)(m0 + lrow) * K + lseg;
    const __half* Bp = Bt + (size_t)(n0 + lrow) * K + lseg;

    const int NCH = K >> 5;

    auto load_stage = [&](int st, int ch) {
        const int koff = ch * 32;
        __half* as = Asm + st * STG_H + lrow * PH + lseg;
        __half* bs = Bsm + st * STG_H + lrow * PH + lseg;
        cp_async16(smem_u32(as),     Ap + koff);
        cp_async16(smem_u32(as + 8), Ap + koff + 8);
        cp_async16(smem_u32(bs),     Bp + koff);
        cp_async16(smem_u32(bs + 8), Bp + koff + 8);
        cp_commit();
    };

    load_stage(0, 0);
    load_stage(1, 1);
    load_stage(2, 2);

    const int a_ro = ((lm8 & 1) << 3) + l8;
    const int a_co = (lm8 >> 1) << 3;
    const int b_ro = ((lm8 >> 1) << 3) + l8;
    const int b_co = (lm8 & 1) << 3;

    for (int ch = 0; ch < NCH; ch++) {
        const int buf = ch % NSTG;
        cp_wait<2>();
        __syncthreads();

        if (ch + 3 < NCH) load_stage((ch + 3) % NSTG, ch + 3);
        else              cp_commit();

        const __half* as = Asm + buf * STG_H;
        const __half* bs = Bsm + buf * STG_H;

        #pragma unroll
        for (int ks = 0; ks < 2; ks++) {
            uint32_t a[4][4], b[4][2];
            #pragma unroll
            for (int mt = 0; mt < 4; mt++)
                ldmatrix_x4(a[mt],
                    smem_u32(as + (wm + mt * 16 + a_ro) * PH + ks * 16 + a_co));
            #pragma unroll
            for (int np = 0; np < 2; np++) {
                uint32_t r[4];
                ldmatrix_x4(r,
                    smem_u32(bs + (wn + np * 16 + b_ro) * PH + ks * 16 + b_co));
                b[2*np    ][0] = r[0]; b[2*np    ][1] = r[1];
                b[2*np + 1][0] = r[2]; b[2*np + 1][1] = r[3];
            }
            #pragma unroll
            for (int mt = 0; mt < 4; mt++)
                #pragma unroll
                for (int nt = 0; nt < 4; nt++)
                    mma_f16(c[mt][nt], a[mt], b[nt]);
        }
    }

    // ---- epilogue ----
    if (OUT == 3) {
        const int seg   = n0 >> 10;
        const int nbase = (n0 & 1023) + wn;
        const float* bp = (seg == 0) ? bias : (seg == 1 ? bias2 : bias3);
        #pragma unroll
        for (int mt = 0; mt < 4; mt++) {
            #pragma unroll
            for (int half_ = 0; half_ < 2; half_++) {
                const int gm = m0 + wm + mt * 16 + qr + half_ * 8;
                #pragma unroll
                for (int nt = 0; nt < 4; nt++) {
                    const int col = nbase + nt * 8 + qc * 2;
                    float v0 = c[mt][nt][half_ * 2 + 0] + bp[col];
                    float v1 = c[mt][nt][half_ * 2 + 1] + bp[col + 1];
                    if (seg == 0) {
                        v0 *= QSCL; v1 *= QSCL;
                        *(__half2*)&g_q[(size_t)gm * DM + col] = __floats2half2_rn(v0, v1);
                    } else if (seg == 1) {
                        *(__half2*)&g_k[(size_t)gm * DM + col] = __floats2half2_rn(v0, v1);
                    } else {
                        const int bb = gm >> 11, s = gm & 2047;
                        g_vt[((size_t)bb * DM + col    ) * SEQ + s] = __float2half_rn(v0);
                        g_vt[((size_t)bb * DM + col + 1) * SEQ + s] = __float2half_rn(v1);
                    }
                }
            }
        }
    } else {
        #pragma unroll
        for (int mt = 0; mt < 4; mt++) {
            #pragma unroll
            for (int half_ = 0; half_ < 2; half_++) {
                const int gm = m0 + wm + mt * 16 + qr + half_ * 8;
                #pragma unroll
                for (int nt = 0; nt < 4; nt++) {
                    const int col = n0 + wn + nt * 8 + qc * 2;
                    float v0 = c[mt][nt][half_ * 2 + 0] + bias[col];
                    float v1 = c[mt][nt][half_ * 2 + 1] + bias[col + 1];
                    if (ACT == 1) { v0 = gelu_exact(v0); v1 = gelu_exact(v1); }
                    if (OUT == 0) {
                        const float2 rv = *(const float2*)&R[(size_t)gm * Mout + col];
                        *(float2*)((float*)Cout + (size_t)gm * Mout + col) =
                            make_float2(v0 + rv.x, v1 + rv.y);
                    } else {
                        *(__half2*)((__half*)Cout + (size_t)gm * Mout + col) =
                            __floats2half2_rn(v0, v1);
                    }
                }
            }
        }
    }
}

// ---------------- fp16 mma flash attention (128 q-rows, 8 warps) -----------
#define PT 72
#define QT_H (128 * PT)               // Q tile: 128 rows
#define KT_H (64 * PT)                // K/V tiles: 64 rows
#define ATTN_SMEM ((QT_H + 2 * KT_H + 2 * KT_H) * 2 + 2 * 64 * 4 + 2 * 64 * 4)

__global__ void __launch_bounds__(256, 2)
attn_kernel(const __half* __restrict__ Q, const __half* __restrict__ K,
            const __half* __restrict__ Vt, const int* __restrict__ mask,
            __half* __restrict__ O)
{
    extern __shared__ __half asm_[];
    __half* Qs = asm_;
    __half* Ks = asm_ + QT_H;
    __half* Vs = asm_ + QT_H + 2 * KT_H;
    int*    mk = (int*)(asm_ + QT_H + 4 * KT_H);
    float*  mb = (float*)(mk + 2 * 64);

    const int tid  = threadIdx.x;
    const int lane = tid & 31, wid = tid >> 5;     // 8 warps, 16 q-rows each
    const int qr = lane >> 2, qc = lane & 3;
    const int lm8 = lane >> 3, l8 = lane & 7;
    const int wm = wid * 16;
    const int b  = blockIdx.z, hh = blockIdx.y;
    const int q0 = blockIdx.x * 128;
    const int bS = b * SEQ;
    const int hoff = hh * DKH;

    // Q loader: 256 threads, one 32-half segment each (128 rows x 64 halfs)
    {
        const int lr = tid >> 1, ls = (tid & 1) * 32;
        const __half* src = Q + (size_t)(bS + q0 + lr) * DM + hoff + ls;
        uint32_t dst = smem_u32(Qs + lr * PT + ls);
        #pragma unroll
        for (int u = 0; u < 4; u++) cp_async16(dst + u * 16, src + u * 8);
        cp_commit();
    }

    const __half* VtBase = Vt + ((size_t)b * DM + hoff) * SEQ;

    // K/V loader: 256 threads, 16 halfs each (64 rows x 64 halfs per tile)
    auto load_kv = [&](int buf, int kv0) {
        const int lr = tid >> 2, ls = (tid & 3) * 16;
        const __half* ks = K + (size_t)(bS + kv0 + lr) * DM + hoff + ls;
        const __half* vs = VtBase + (size_t)lr * SEQ + kv0 + ls;
        uint32_t dk = smem_u32(Ks + buf * KT_H + lr * PT + ls);
        uint32_t dv = smem_u32(Vs + buf * KT_H + lr * PT + ls);
        #pragma unroll
        for (int u = 0; u < 2; u++) {
            cp_async16(dk + u * 16, ks + u * 8);
            cp_async16(dv + u * 16, vs + u * 8);
        }
        if (tid < 16)
            cp_async16(smem_u32(mk + buf * 64 + tid * 4), mask + bS + kv0 + tid * 4);
    };

    load_kv(0, 0);
    cp_commit();
    cp_wait<0>();
    if (tid < 64) mb[tid] = mk[tid] ? 0.f : -1e9f;
    __syncthreads();

    const int a_ro = ((lm8 & 1) << 3) + l8;
    const int a_co = (lm8 >> 1) << 3;
    const int b_ro = ((lm8 >> 1) << 3) + l8;
    const int b_co = (lm8 & 1) << 3;

    uint32_t a_q[4][4];
    #pragma unroll
    for (int ks = 0; ks < 4; ks++)
        ldmatrix_x4(a_q[ks], smem_u32(Qs + (wm + a_ro) * PT + ks * 16 + a_co));

    float c_o[8][4];
    #pragma unroll
    for (int nt = 0; nt < 8; nt++)
        #pragma unroll
        for (int e = 0; e < 4; e++) c_o[nt][e] = 0.f;
    float m0r = -1e30f, m1r = -1e30f, l0r = 0.f, l1r = 0.f;

    const int NT = SEQ / 64;
    for (int t = 0; t < NT; t++) {
        const int buf = t & 1;
        if (t + 1 < NT) { load_kv(buf ^ 1, (t + 1) * 64); cp_commit(); }

        // ---- S = Q K^T (log2 domain) ----
        float c_s[8][4];
        #pragma unroll
        for (int nt = 0; nt < 8; nt++)
            #pragma unroll
            for (int e = 0; e < 4; e++) c_s[nt][e] = 0.f;

        const __half* kb = Ks + buf * KT_H;
        #pragma unroll
        for (int ks = 0; ks < 4; ks++) {
            uint32_t bb[8][2];
            #pragma unroll
            for (int np = 0; np < 4; np++) {
                uint32_t r[4];
                ldmatrix_x4(r, smem_u32(kb + (np * 16 + b_ro) * PT + ks * 16 + b_co));
                bb[2*np    ][0] = r[0]; bb[2*np    ][1] = r[1];
                bb[2*np + 1][0] = r[2]; bb[2*np + 1][1] = r[3];
            }
            #pragma unroll
            for (int nt = 0; nt < 8; nt++)
                mma_f16(c_s[nt], a_q[ks], bb[nt]);
        }

        // ---- mask (additive) + online softmax (base-2) ----
        float mx0 = -1e30f, mx1 = -1e30f;
        #pragma unroll
        for (int nt = 0; nt < 8; nt++) {
            const int c0 = nt * 8 + qc * 2;
            const float b0 = mb[buf * 64 + c0], b1 = mb[buf * 64 + c0 + 1];
            c_s[nt][0] += b0; c_s[nt][1] += b1;
            c_s[nt][2] += b0; c_s[nt][3] += b1;
            mx0 = fmaxf(mx0, fmaxf(c_s[nt][0], c_s[nt][1]));
            mx1 = fmaxf(mx1, fmaxf(c_s[nt][2], c_s[nt][3]));
        }
        #pragma unroll
        for (int off = 1; off < 4; off <<= 1) {
            mx0 = fmaxf(mx0, __shfl_xor_sync(0xffffffffu, mx0, off));
            mx1 = fmaxf(mx1, __shfl_xor_sync(0xffffffffu, mx1, off));
        }
        const float mn0 = fmaxf(m0r, mx0), mn1 = fmaxf(m1r, mx1);
        const float al0 = ex2f(m0r - mn0), al1 = ex2f(m1r - mn1);
        float s0 = 0.f, s1 = 0.f;
        #pragma unroll
        for (int nt = 0; nt < 8; nt++) {
            c_s[nt][0] = ex2f(c_s[nt][0] - mn0);
            c_s[nt][1] = ex2f(c_s[nt][1] - mn0);
            c_s[nt][2] = ex2f(c_s[nt][2] - mn1);
            c_s[nt][3] = ex2f(c_s[nt][3] - mn1);
            s0 += c_s[nt][0] + c_s[nt][1];
            s1 += c_s[nt][2] + c_s[nt][3];
        }
        #pragma unroll
        for (int off = 1; off < 4; off <<= 1) {
            s0 += __shfl_xor_sync(0xffffffffu, s0, off);
            s1 += __shfl_xor_sync(0xffffffffu, s1, off);
        }
        l0r = l0r * al0 + s0;  m0r = mn0;
        l1r = l1r * al1 + s1;  m1r = mn1;
        #pragma unroll
        for (int nt = 0; nt < 8; nt++) {
            c_o[nt][0] *= al0; c_o[nt][1] *= al0;
            c_o[nt][2] *= al1; c_o[nt][3] *= al1;
        }

        uint32_t ap[4][4];
        #pragma unroll
        for (int ks = 0; ks < 4; ks++) {
            ap[ks][0] = pack_h2(c_s[2*ks    ][0], c_s[2*ks    ][1]);
            ap[ks][1] = pack_h2(c_s[2*ks    ][2], c_s[2*ks    ][3]);
            ap[ks][2] = pack_h2(c_s[2*ks + 1][0], c_s[2*ks + 1][1]);
            ap[ks][3] = pack_h2(c_s[2*ks + 1][2], c_s[2*ks + 1][3]);
        }

        const __half* vb = Vs + buf * KT_H;
        #pragma unroll
        for (int ks = 0; ks < 4; ks++) {
            uint32_t bb[8][2];
            #pragma unroll
            for (int np = 0; np < 4; np++) {
                uint32_t r[4];
                ldmatrix_x4(r, smem_u32(vb + (np * 16 + b_ro) * PT + ks * 16 + b_co));
                bb[2*np    ][0] = r[0]; bb[2*np    ][1] = r[1];
                bb[2*np + 1][0] = r[2]; bb[2*np + 1][1] = r[3];
            }
            #pragma unroll
            for (int nt = 0; nt < 8; nt++)
                mma_f16(c_o[nt], ap[ks], bb[nt]);
        }

        if (t + 1 < NT) {
            cp_wait<0>();
            if (tid < 64)
                mb[(buf ^ 1) * 64 + tid] = mk[(buf ^ 1) * 64 + tid] ? 0.f : -1e9f;
        }
        __syncthreads();
    }

    const float i0 = 1.f / l0r, i1 = 1.f / l1r;
    #pragma unroll
    for (int nt = 0; nt < 8; nt++) {
        const size_t r0 = (size_t)(bS + q0 + wm + qr);
        const int col = hoff + nt * 8 + qc * 2;
        *(__half2*)&O[r0 * DM + col] =
            __floats2half2_rn(c_o[nt][0] * i0, c_o[nt][1] * i0);
        *(__half2*)&O[(r0 + 8) * DM + col] =
            __floats2half2_rn(c_o[nt][2] * i1, c_o[nt][3] * i1);
    }
}

// ---------------- launch ---------------------------------------------------
extern "C" void kernel_launch(void* const* d_in, const int* in_sizes, int n_in,
                              void* d_out, int out_size)
{
    const float* x    = (const float*)d_in[0];
    const int*   mask = (const int*)  d_in[1];
    const float* Wq   = (const float*)d_in[2];
    const float* bq   = (const float*)d_in[3];
    const float* Wk   = (const float*)d_in[4];
    const float* bk   = (const float*)d_in[5];
    const float* Wv   = (const float*)d_in[6];
    const float* bv   = (const float*)d_in[7];
    const float* Wo   = (const float*)d_in[8];
    const float* bo   = (const float*)d_in[9];
    const float* W1   = (const float*)d_in[10];
    const float* b1   = (const float*)d_in[11];
    const float* W2   = (const float*)d_in[12];
    const float* b2   = (const float*)d_in[13];
    const float* g1   = (const float*)d_in[14];
    const float* be1  = (const float*)d_in[15];
    const float* g2   = (const float*)d_in[16];
    const float* be2  = (const float*)d_in[17];
    float* out = (float*)d_out;

    __half *h, *q, *k, *vt, *att, *h2, *ff;
    float  *x1;
    __half *wqkvt, *wot, *w1t, *w2t;
    cudaGetSymbolAddress((void**)&h,     g_h);
    cudaGetSymbolAddress((void**)&q,     g_q);
    cudaGetSymbolAddress((void**)&k,     g_k);
    cudaGetSymbolAddress((void**)&vt,    g_vt);
    cudaGetSymbolAddress((void**)&att,   g_att);
    cudaGetSymbolAddress((void**)&x1,    g_x1);
    cudaGetSymbolAddress((void**)&h2,    g_h2);
    cudaGetSymbolAddress((void**)&ff,    g_ff);
    cudaGetSymbolAddress((void**)&wqkvt, g_wqkvt);
    cudaGetSymbolAddress((void**)&wot,   g_wot);
    cudaGetSymbolAddress((void**)&w1t,   g_w1t);
    cudaGetSymbolAddress((void**)&w2t,   g_w2t);

    cudaFuncSetAttribute(attn_kernel,
                         cudaFuncAttributeMaxDynamicSharedMemorySize, ATTN_SMEM);
    cudaFuncSetAttribute(mma_gemm<0, 0>,
                         cudaFuncAttributeMaxDynamicSharedMemorySize, GEMM_SMEM);
    cudaFuncSetAttribute(mma_gemm<0, 1>,
                         cudaFuncAttributeMaxDynamicSharedMemorySize, GEMM_SMEM);
    cudaFuncSetAttribute(mma_gemm<0, 3>,
                         cudaFuncAttributeMaxDynamicSharedMemorySize, GEMM_SMEM);
    cudaFuncSetAttribute(mma_gemm<1, 1>,
                         cudaFuncAttributeMaxDynamicSharedMemorySize, GEMM_SMEM);

    tr6_kernel<<<12288, 256>>>(Wq, Wk, Wv, Wo, W1, W2, wqkvt, wot, w1t, w2t);

    ln_kernel<<<NTOK, 256>>>(x, g1, be1, h);
    mma_gemm<0, 3><<<dim3(3 * DM / 128, NTOK / 128), 256, GEMM_SMEM>>>(
        h, wqkvt, bq, bk, bv, nullptr, nullptr, DM, 3 * DM);
    attn_kernel<<<dim3(SEQ / 128, NH, NB), 256, ATTN_SMEM>>>(q, k, vt, mask, att);
    mma_gemm<0, 0><<<dim3(DM / 128, NTOK / 128), 256, GEMM_SMEM>>>(
        att, wot, bo, nullptr, nullptr, x, x1, DM, DM);
    ln_kernel<<<NTOK, 256>>>(x1, g2, be2, h2);
    mma_gemm<1, 1><<<dim3(DFF / 128, NTOK / 128), 256, GEMM_SMEM>>>(
        h2, w1t, b1, nullptr, nullptr, nullptr, ff, DM, DFF);
    mma_gemm<0, 0><<<dim3(DM / 128, NTOK / 128), 256, GEMM_SMEM>>>(
        ff, w2t, b2, nullptr, nullptr, x1, out, DFF, DM);
}

// round 17
// speedup vs baseline: 1.2154x; 1.0048x over previous
#include <cuda_runtime.h>
#include <cuda_fp16.h>
#include <math.h>
#include <stdint.h>

#define NTOK 8192
#define DM   1024
#define DFF  4096
#define SEQ  2048
#define NB   4
#define NH   16
#define DKH  64

// 0.125 (1/sqrt(dk)) * log2(e): folded into Q projection; attention uses ex2.
#define QSCL 0.18033688011112042f

// ---------------- scratch (device globals: allocation-guard safe) ----------
__device__ __half g_h  [(size_t)NTOK * DM];
__device__ __half g_q  [(size_t)NTOK * DM];
__device__ __half g_k  [(size_t)NTOK * DM];
__device__ __half g_vt [(size_t)NB * DM * SEQ];   // V transposed: [b][col][s]
__device__ __half g_att[(size_t)NTOK * DM];
__device__ float  g_x1 [(size_t)NTOK * DM];
__device__ __half g_h2 [(size_t)NTOK * DM];
__device__ __half g_ff [(size_t)NTOK * DFF];
__device__ __half g_wqkvt[(size_t)3 * DM * DM];   // concat W{q,k,v}^T
__device__ __half g_wot[(size_t)DM * DM];
__device__ __half g_w1t[(size_t)DFF * DM];
__device__ __half g_w2t[(size_t)DM * DFF];

// ---------------- helpers ---------------------------------------------------
__device__ __forceinline__ uint32_t smem_u32(const void* p) {
    uint32_t a;
    asm("{ .reg .u64 t; cvta.to.shared.u64 t, %1; cvt.u32.u64 %0, t; }"
        : "=r"(a) : "l"(p));
    return a;
}
__device__ __forceinline__ void cp_async16(uint32_t dst, const void* src) {
    asm volatile("cp.async.cg.shared.global [%0], [%1], 16;" :: "r"(dst), "l"(src));
}
__device__ __forceinline__ void cp_commit() {
    asm volatile("cp.async.commit_group;" ::: "memory");
}
template <int N>
__device__ __forceinline__ void cp_wait() {
    asm volatile("cp.async.wait_group %0;" :: "n"(N) : "memory");
}
__device__ __forceinline__ void ldmatrix_x4(uint32_t* r, uint32_t addr) {
    asm volatile("ldmatrix.sync.aligned.m8n8.x4.shared.b16 {%0,%1,%2,%3}, [%4];"
                 : "=r"(r[0]), "=r"(r[1]), "=r"(r[2]), "=r"(r[3]) : "r"(addr));
}
__device__ __forceinline__ void mma_f16(float* c, const uint32_t* a, const uint32_t* b) {
    asm volatile(
        "mma.sync.aligned.m16n8k16.row.col.f32.f16.f16.f32 "
        "{%0,%1,%2,%3}, {%4,%5,%6,%7}, {%8,%9}, {%0,%1,%2,%3};"
        : "+f"(c[0]), "+f"(c[1]), "+f"(c[2]), "+f"(c[3])
        : "r"(a[0]), "r"(a[1]), "r"(a[2]), "r"(a[3]), "r"(b[0]), "r"(b[1]));
}
__device__ __forceinline__ uint32_t pack_h2(float lo, float hi) {
    __half2 h = __floats2half2_rn(lo, hi);
    return *(uint32_t*)&h;
}
__device__ __forceinline__ float ex2f(float x) {
    float y;
    asm("ex2.approx.ftz.f32 %0, %1;" : "=f"(y) : "f"(x));
    return y;
}
__device__ __forceinline__ float gelu_exact(float v)
{
    return 0.5f * v * (1.0f + erff(v * 0.70710678118654752f));
}

// ---------------- merged weight transpose (6 jobs, 1 launch) ---------------
__global__ void __launch_bounds__(256)
tr6_kernel(const float* __restrict__ Wq, const float* __restrict__ Wk,
           const float* __restrict__ Wv, const float* __restrict__ Wo,
           const float* __restrict__ W1, const float* __restrict__ W2,
           __half* __restrict__ wqkvt, __half* __restrict__ wot,
           __half* __restrict__ w1t,   __half* __restrict__ w2t)
{
    const int id = blockIdx.x;
    int job, base;
    if (id < 4096)      { job = id >> 10; base = id & 1023; }
    else if (id < 8192) { job = 4; base = id - 4096; }
    else                { job = 5; base = id - 8192; }

    const float* in; __half* out; int rows, cols, gx;
    switch (job) {
        case 0: in = Wq; out = wqkvt;                       rows = DM;  cols = DM;  gx = 32;  break;
        case 1: in = Wk; out = wqkvt + (size_t)DM * DM;     rows = DM;  cols = DM;  gx = 32;  break;
        case 2: in = Wv; out = wqkvt + (size_t)2 * DM * DM; rows = DM;  cols = DM;  gx = 32;  break;
        case 3: in = Wo; out = wot;                         rows = DM;  cols = DM;  gx = 32;  break;
        case 4: in = W1; out = w1t;                         rows = DM;  cols = DFF; gx = 128; break;
        default:in = W2; out = w2t;                         rows = DFF; cols = DM;  gx = 32;  break;
    }
    const int bx = base % gx, by = base / gx;

    __shared__ float t[32][33];
    const int tx = threadIdx.x & 31, ty = threadIdx.x >> 5;
    const int x  = bx * 32 + tx;
    const int y0 = by * 32;
    #pragma unroll
    for (int j = ty; j < 32; j += 8)
        t[j][tx] = in[(size_t)(y0 + j) * cols + x];
    __syncthreads();
    const int ox  = y0 + tx;
    const int oy0 = bx * 32;
    #pragma unroll
    for (int j = ty; j < 32; j += 8)
        out[(size_t)(oy0 + j) * rows + ox] = __float2half_rn(t[tx][j]);
}

// ---------------- LayerNorm (fp32 in -> fp16 out; only feeds GEMMs) --------
__global__ void __launch_bounds__(256)
ln_kernel(const float* __restrict__ x, const float* __restrict__ gam,
          const float* __restrict__ bet, __half* __restrict__ out)
{
    const int row = blockIdx.x;
    const float4 v = ((const float4*)(x + (size_t)row * DM))[threadIdx.x];
    float s = v.x + v.y + v.z + v.w;
    float q = v.x*v.x + v.y*v.y + v.z*v.z + v.w*v.w;
    #pragma unroll
    for (int o = 16; o; o >>= 1) {
        s += __shfl_xor_sync(0xffffffffu, s, o);
        q += __shfl_xor_sync(0xffffffffu, q, o);
    }
    __shared__ float ss[8], sq[8];
    const int w = threadIdx.x >> 5, l = threadIdx.x & 31;
    if (l == 0) { ss[w] = s; sq[w] = q; }
    __syncthreads();
    if (w == 0) {
        s = (l < 8) ? ss[l] : 0.f;
        q = (l < 8) ? sq[l] : 0.f;
        #pragma unroll
        for (int o = 4; o; o >>= 1) {
            s += __shfl_xor_sync(0xffffffffu, s, o);
            q += __shfl_xor_sync(0xffffffffu, q, o);
        }
        if (l == 0) { ss[0] = s; sq[0] = q; }
    }
    __syncthreads();
    const float mean = ss[0] * (1.f / DM);
    const float var  = sq[0] * (1.f / DM) - mean * mean;
    const float rstd = rsqrtf(var + 1e-5f);
    const float4 g4 = ((const float4*)gam)[threadIdx.x];
    const float4 b4 = ((const float4*)bet)[threadIdx.x];
    __half2* o2 = (__half2*)(out + (size_t)row * DM);
    o2[threadIdx.x * 2    ] = __floats2half2_rn((v.x - mean) * rstd * g4.x + b4.x,
                                                (v.y - mean) * rstd * g4.y + b4.y);
    o2[threadIdx.x * 2 + 1] = __floats2half2_rn((v.z - mean) * rstd * g4.z + b4.z,
                                                (v.w - mean) * rstd * g4.w + b4.w);
}

// ---------------- fp16 mma GEMM (4-stage cp.async + ldmatrix) --------------
#define PH 40
#define STG_H (128 * PH)
#define NSTG 4
#define GEMM_SMEM (NSTG * 2 * STG_H * 2)

template <int ACT, int OUT>
__global__ void __launch_bounds__(256, 2)
mma_gemm(const __half* __restrict__ A, const __half* __restrict__ Bt,
         const float* __restrict__ bias, const float* __restrict__ bias2,
         const float* __restrict__ bias3, const float* __restrict__ R,
         void* __restrict__ Cout, int K, int Mout)
{
    extern __shared__ __half hsm[];
    __half* Asm = hsm;
    __half* Bsm = hsm + NSTG * STG_H;

    const int tid  = threadIdx.x;
    const int lane = tid & 31, wid = tid >> 5;
    const int wm = (wid >> 2) * 64;
    const int wn = (wid & 3) * 32;
    const int qr = lane >> 2, qc = lane & 3;
    const int lm8 = lane >> 3;
    const int l8  = lane & 7;
    const int m0 = blockIdx.y * 128, n0 = blockIdx.x * 128;

    float c[4][4][4];
    #pragma unroll
    for (int i = 0; i < 4; i++)
        #pragma unroll
        for (int j = 0; j < 4; j++)
            #pragma unroll
            for (int e = 0; e < 4; e++) c[i][j][e] = 0.f;

    const int lrow = tid >> 1;
    const int lseg = (tid & 1) * 16;
    const __half* Ap = A  + (size_t)(m0 + lrow) * K + lseg;
    const __half* Bp = Bt + (size_t)(n0 + lrow) * K + lseg;

    const int NCH = K >> 5;

    auto load_stage = [&](int st, int ch) {
        const int koff = ch * 32;
        __half* as = Asm + st * STG_H + lrow * PH + lseg;
        __half* bs = Bsm + st * STG_H + lrow * PH + lseg;
        cp_async16(smem_u32(as),     Ap + koff);
        cp_async16(smem_u32(as + 8), Ap + koff + 8);
        cp_async16(smem_u32(bs),     Bp + koff);
        cp_async16(smem_u32(bs + 8), Bp + koff + 8);
        cp_commit();
    };

    load_stage(0, 0);
    load_stage(1, 1);
    load_stage(2, 2);

    const int a_ro = ((lm8 & 1) << 3) + l8;
    const int a_co = (lm8 >> 1) << 3;
    const int b_ro = ((lm8 >> 1) << 3) + l8;
    const int b_co = (lm8 & 1) << 3;

    for (int ch = 0; ch < NCH; ch++) {
        const int buf = ch % NSTG;
        cp_wait<2>();
        __syncthreads();

        if (ch + 3 < NCH) load_stage((ch + 3) % NSTG, ch + 3);
        else              cp_commit();

        const __half* as = Asm + buf * STG_H;
        const __half* bs = Bsm + buf * STG_H;

        #pragma unroll
        for (int ks = 0; ks < 2; ks++) {
            uint32_t a[4][4], b[4][2];
            #pragma unroll
            for (int mt = 0; mt < 4; mt++)
                ldmatrix_x4(a[mt],
                    smem_u32(as + (wm + mt * 16 + a_ro) * PH + ks * 16 + a_co));
            #pragma unroll
            for (int np = 0; np < 2; np++) {
                uint32_t r[4];
                ldmatrix_x4(r,
                    smem_u32(bs + (wn + np * 16 + b_ro) * PH + ks * 16 + b_co));
                b[2*np    ][0] = r[0]; b[2*np    ][1] = r[1];
                b[2*np + 1][0] = r[2]; b[2*np + 1][1] = r[3];
            }
            #pragma unroll
            for (int mt = 0; mt < 4; mt++)
                #pragma unroll
                for (int nt = 0; nt < 4; nt++)
                    mma_f16(c[mt][nt], a[mt], b[nt]);
        }
    }

    // ---- epilogue ----
    if (OUT == 3) {
        const int seg   = n0 >> 10;
        const int nbase = (n0 & 1023) + wn;
        const float* bp = (seg == 0) ? bias : (seg == 1 ? bias2 : bias3);
        #pragma unroll
        for (int mt = 0; mt < 4; mt++) {
            #pragma unroll
            for (int half_ = 0; half_ < 2; half_++) {
                const int gm = m0 + wm + mt * 16 + qr + half_ * 8;
                #pragma unroll
                for (int nt = 0; nt < 4; nt++) {
                    const int col = nbase + nt * 8 + qc * 2;
                    float v0 = c[mt][nt][half_ * 2 + 0] + bp[col];
                    float v1 = c[mt][nt][half_ * 2 + 1] + bp[col + 1];
                    if (seg == 0) {
                        v0 *= QSCL; v1 *= QSCL;
                        *(__half2*)&g_q[(size_t)gm * DM + col] = __floats2half2_rn(v0, v1);
                    } else if (seg == 1) {
                        *(__half2*)&g_k[(size_t)gm * DM + col] = __floats2half2_rn(v0, v1);
                    } else {
                        const int bb = gm >> 11, s = gm & 2047;
                        g_vt[((size_t)bb * DM + col    ) * SEQ + s] = __float2half_rn(v0);
                        g_vt[((size_t)bb * DM + col + 1) * SEQ + s] = __float2half_rn(v1);
                    }
                }
            }
        }
    } else {
        #pragma unroll
        for (int mt = 0; mt < 4; mt++) {
            #pragma unroll
            for (int half_ = 0; half_ < 2; half_++) {
                const int gm = m0 + wm + mt * 16 + qr + half_ * 8;
                #pragma unroll
                for (int nt = 0; nt < 4; nt++) {
                    const int col = n0 + wn + nt * 8 + qc * 2;
                    float v0 = c[mt][nt][half_ * 2 + 0] + bias[col];
                    float v1 = c[mt][nt][half_ * 2 + 1] + bias[col + 1];
                    if (ACT == 1) { v0 = gelu_exact(v0); v1 = gelu_exact(v1); }
                    if (OUT == 0) {
                        const float2 rv = *(const float2*)&R[(size_t)gm * Mout + col];
                        *(float2*)((float*)Cout + (size_t)gm * Mout + col) =
                            make_float2(v0 + rv.x, v1 + rv.y);
                    } else {
                        *(__half2*)((__half*)Cout + (size_t)gm * Mout + col) =
                            __floats2half2_rn(v0, v1);
                    }
                }
            }
        }
    }
}

// ---------------- fp16 mma flash attention (128 q-rows, 8 warps) -----------
#define PT 72
#define QT_H (128 * PT)               // Q tile: 128 rows
#define KT_H (64 * PT)                // K/V tiles: 64 rows
#define ATTN_SMEM ((QT_H + 2 * KT_H + 2 * KT_H) * 2 + 2 * 64 * 4 + 2 * 64 * 4)

__global__ void __launch_bounds__(256, 2)
attn_kernel(const __half* __restrict__ Q, const __half* __restrict__ K,
            const __half* __restrict__ Vt, const int* __restrict__ mask,
            __half* __restrict__ O)
{
    extern __shared__ __half asm_[];
    __half* Qs = asm_;
    __half* Ks = asm_ + QT_H;
    __half* Vs = asm_ + QT_H + 2 * KT_H;
    int*    mk = (int*)(asm_ + QT_H + 4 * KT_H);
    float*  mb = (float*)(mk + 2 * 64);

    const int tid  = threadIdx.x;
    const int lane = tid & 31, wid = tid >> 5;     // 8 warps, 16 q-rows each
    const int qr = lane >> 2, qc = lane & 3;
    const int lm8 = lane >> 3, l8 = lane & 7;
    const int wm = wid * 16;
    const int b  = blockIdx.z, hh = blockIdx.y;
    const int q0 = blockIdx.x * 128;
    const int bS = b * SEQ;
    const int hoff = hh * DKH;

    // Q loader: 256 threads, one 32-half segment each (128 rows x 64 halfs)
    {
        const int lr = tid >> 1, ls = (tid & 1) * 32;
        const __half* src = Q + (size_t)(bS + q0 + lr) * DM + hoff + ls;
        uint32_t dst = smem_u32(Qs + lr * PT + ls);
        #pragma unroll
        for (int u = 0; u < 4; u++) cp_async16(dst + u * 16, src + u * 8);
        cp_commit();
    }

    const __half* VtBase = Vt + ((size_t)b * DM + hoff) * SEQ;

    // K/V loader: 256 threads, 16 halfs each (64 rows x 64 halfs per tile)
    auto load_kv = [&](int buf, int kv0) {
        const int lr = tid >> 2, ls = (tid & 3) * 16;
        const __half* ks = K + (size_t)(bS + kv0 + lr) * DM + hoff + ls;
        const __half* vs = VtBase + (size_t)lr * SEQ + kv0 + ls;
        uint32_t dk = smem_u32(Ks + buf * KT_H + lr * PT + ls);
        uint32_t dv = smem_u32(Vs + buf * KT_H + lr * PT + ls);
        #pragma unroll
        for (int u = 0; u < 2; u++) {
            cp_async16(dk + u * 16, ks + u * 8);
            cp_async16(dv + u * 16, vs + u * 8);
        }
        if (tid < 16)
            cp_async16(smem_u32(mk + buf * 64 + tid * 4), mask + bS + kv0 + tid * 4);
    };

    load_kv(0, 0);
    cp_commit();
    cp_wait<0>();
    if (tid < 64) mb[tid] = mk[tid] ? 0.f : -1e9f;
    __syncthreads();

    const int a_ro = ((lm8 & 1) << 3) + l8;
    const int a_co = (lm8 >> 1) << 3;
    const int b_ro = ((lm8 >> 1) << 3) + l8;
    const int b_co = (lm8 & 1) << 3;

    uint32_t a_q[4][4];
    #pragma unroll
    for (int ks = 0; ks < 4; ks++)
        ldmatrix_x4(a_q[ks], smem_u32(Qs + (wm + a_ro) * PT + ks * 16 + a_co));

    float c_o[8][4];
    #pragma unroll
    for (int nt = 0; nt < 8; nt++)
        #pragma unroll
        for (int e = 0; e < 4; e++) c_o[nt][e] = 0.f;
    float m0r = -1e30f, m1r = -1e30f, l0r = 0.f, l1r = 0.f;

    const int NT = SEQ / 64;

    // body with compile-time buf: all smem fragment addresses constant-fold
    auto body = [&](const int buf, const int t) {
        if (t + 1 < NT) { load_kv(buf ^ 1, (t + 1) * 64); cp_commit(); }

        float c_s[8][4];
        #pragma unroll
        for (int nt = 0; nt < 8; nt++)
            #pragma unroll
            for (int e = 0; e < 4; e++) c_s[nt][e] = 0.f;

        const __half* kb = Ks + buf * KT_H;
        #pragma unroll
        for (int ks = 0; ks < 4; ks++) {
            uint32_t bb[8][2];
            #pragma unroll
            for (int np = 0; np < 4; np++) {
                uint32_t r[4];
                ldmatrix_x4(r, smem_u32(kb + (np * 16 + b_ro) * PT + ks * 16 + b_co));
                bb[2*np    ][0] = r[0]; bb[2*np    ][1] = r[1];
                bb[2*np + 1][0] = r[2]; bb[2*np + 1][1] = r[3];
            }
            #pragma unroll
            for (int nt = 0; nt < 8; nt++)
                mma_f16(c_s[nt], a_q[ks], bb[nt]);
        }

        float mx0 = -1e30f, mx1 = -1e30f;
        #pragma unroll
        for (int nt = 0; nt < 8; nt++) {
            const int c0 = nt * 8 + qc * 2;
            const float b0 = mb[buf * 64 + c0], b1 = mb[buf * 64 + c0 + 1];
            c_s[nt][0] += b0; c_s[nt][1] += b1;
            c_s[nt][2] += b0; c_s[nt][3] += b1;
            mx0 = fmaxf(mx0, fmaxf(c_s[nt][0], c_s[nt][1]));
            mx1 = fmaxf(mx1, fmaxf(c_s[nt][2], c_s[nt][3]));
        }
        #pragma unroll
        for (int off = 1; off < 4; off <<= 1) {
            mx0 = fmaxf(mx0, __shfl_xor_sync(0xffffffffu, mx0, off));
            mx1 = fmaxf(mx1, __shfl_xor_sync(0xffffffffu, mx1, off));
        }
        const float mn0 = fmaxf(m0r, mx0), mn1 = fmaxf(m1r, mx1);
        const float al0 = ex2f(m0r - mn0), al1 = ex2f(m1r - mn1);
        float s0 = 0.f, s1 = 0.f;
        #pragma unroll
        for (int nt = 0; nt < 8; nt++) {
            c_s[nt][0] = ex2f(c_s[nt][0] - mn0);
            c_s[nt][1] = ex2f(c_s[nt][1] - mn0);
            c_s[nt][2] = ex2f(c_s[nt][2] - mn1);
            c_s[nt][3] = ex2f(c_s[nt][3] - mn1);
            s0 += c_s[nt][0] + c_s[nt][1];
            s1 += c_s[nt][2] + c_s[nt][3];
        }
        #pragma unroll
        for (int off = 1; off < 4; off <<= 1) {
            s0 += __shfl_xor_sync(0xffffffffu, s0, off);
            s1 += __shfl_xor_sync(0xffffffffu, s1, off);
        }
        l0r = l0r * al0 + s0;  m0r = mn0;
        l1r = l1r * al1 + s1;  m1r = mn1;
        #pragma unroll
        for (int nt = 0; nt < 8; nt++) {
            c_o[nt][0] *= al0; c_o[nt][1] *= al0;
            c_o[nt][2] *= al1; c_o[nt][3] *= al1;
        }

        uint32_t ap[4][4];
        #pragma unroll
        for (int ks = 0; ks < 4; ks++) {
            ap[ks][0] = pack_h2(c_s[2*ks    ][0], c_s[2*ks    ][1]);
            ap[ks][1] = pack_h2(c_s[2*ks    ][2], c_s[2*ks    ][3]);
            ap[ks][2] = pack_h2(c_s[2*ks + 1][0], c_s[2*ks + 1][1]);
            ap[ks][3] = pack_h2(c_s[2*ks + 1][2], c_s[2*ks + 1][3]);
        }

        const __half* vb = Vs + buf * KT_H;
        #pragma unroll
        for (int ks = 0; ks < 4; ks++) {
            uint32_t bb[8][2];
            #pragma unroll
            for (int np = 0; np < 4; np++) {
                uint32_t r[4];
                ldmatrix_x4(r, smem_u32(vb + (np * 16 + b_ro) * PT + ks * 16 + b_co));
                bb[2*np    ][0] = r[0]; bb[2*np    ][1] = r[1];
                bb[2*np + 1][0] = r[2]; bb[2*np + 1][1] = r[3];
            }
            #pragma unroll
            for (int nt = 0; nt < 8; nt++)
                mma_f16(c_o[nt], ap[ks], bb[nt]);
        }

        if (t + 1 < NT) {
            cp_wait<0>();
            if (tid < 64)
                mb[(buf ^ 1) * 64 + tid] = mk[(buf ^ 1) * 64 + tid] ? 0.f : -1e9f;
        }
        __syncthreads();
    };

    for (int t = 0; t < NT; t += 2) {
        body(0, t);
        body(1, t + 1);
    }

    const float i0 = 1.f / l0r, i1 = 1.f / l1r;
    #pragma unroll
    for (int nt = 0; nt < 8; nt++) {
        const size_t r0 = (size_t)(bS + q0 + wm + qr);
        const int col = hoff + nt * 8 + qc * 2;
        *(__half2*)&O[r0 * DM + col] =
            __floats2half2_rn(c_o[nt][0] * i0, c_o[nt][1] * i0);
        *(__half2*)&O[(r0 + 8) * DM + col] =
            __floats2half2_rn(c_o[nt][2] * i1, c_o[nt][3] * i1);
    }
}

// ---------------- launch ---------------------------------------------------
extern "C" void kernel_launch(void* const* d_in, const int* in_sizes, int n_in,
                              void* d_out, int out_size)
{
    const float* x    = (const float*)d_in[0];
    const int*   mask = (const int*)  d_in[1];
    const float* Wq   = (const float*)d_in[2];
    const float* bq   = (const float*)d_in[3];
    const float* Wk   = (const float*)d_in[4];
    const float* bk   = (const float*)d_in[5];
    const float* Wv   = (const float*)d_in[6];
    const float* bv   = (const float*)d_in[7];
    const float* Wo   = (const float*)d_in[8];
    const float* bo   = (const float*)d_in[9];
    const float* W1   = (const float*)d_in[10];
    const float* b1   = (const float*)d_in[11];
    const float* W2   = (const float*)d_in[12];
    const float* b2   = (const float*)d_in[13];
    const float* g1   = (const float*)d_in[14];
    const float* be1  = (const float*)d_in[15];
    const float* g2   = (const float*)d_in[16];
    const float* be2  = (const float*)d_in[17];
    float* out = (float*)d_out;

    __half *h, *q, *k, *vt, *att, *h2, *ff;
    float  *x1;
    __half *wqkvt, *wot, *w1t, *w2t;
    cudaGetSymbolAddress((void**)&h,     g_h);
    cudaGetSymbolAddress((void**)&q,     g_q);
    cudaGetSymbolAddress((void**)&k,     g_k);
    cudaGetSymbolAddress((void**)&vt,    g_vt);
    cudaGetSymbolAddress((void**)&att,   g_att);
    cudaGetSymbolAddress((void**)&x1,    g_x1);
    cudaGetSymbolAddress((void**)&h2,    g_h2);
    cudaGetSymbolAddress((void**)&ff,    g_ff);
    cudaGetSymbolAddress((void**)&wqkvt, g_wqkvt);
    cudaGetSymbolAddress((void**)&wot,   g_wot);
    cudaGetSymbolAddress((void**)&w1t,   g_w1t);
    cudaGetSymbolAddress((void**)&w2t,   g_w2t);

    cudaFuncSetAttribute(attn_kernel,
                         cudaFuncAttributeMaxDynamicSharedMemorySize, ATTN_SMEM);
    cudaFuncSetAttribute(mma_gemm<0, 0>,
                         cudaFuncAttributeMaxDynamicSharedMemorySize, GEMM_SMEM);
    cudaFuncSetAttribute(mma_gemm<0, 1>,
                         cudaFuncAttributeMaxDynamicSharedMemorySize, GEMM_SMEM);
    cudaFuncSetAttribute(mma_gemm<0, 3>,
                         cudaFuncAttributeMaxDynamicSharedMemorySize, GEMM_SMEM);
    cudaFuncSetAttribute(mma_gemm<1, 1>,
                         cudaFuncAttributeMaxDynamicSharedMemorySize, GEMM_SMEM);

    tr6_kernel<<<12288, 256>>>(Wq, Wk, Wv, Wo, W1, W2, wqkvt, wot, w1t, w2t);

    ln_kernel<<<NTOK, 256>>>(x, g1, be1, h);
    mma_gemm<0, 3><<<dim3(3 * DM / 128, NTOK / 128), 256, GEMM_SMEM>>>(
        h, wqkvt, bq, bk, bv, nullptr, nullptr, DM, 3 * DM);
    attn_kernel<<<dim3(SEQ / 128, NH, NB), 256, ATTN_SMEM>>>(q, k, vt, mask, att);
    mma_gemm<0, 0><<<dim3(DM / 128, NTOK / 128), 256, GEMM_SMEM>>>(
        att, wot, bo, nullptr, nullptr, x, x1, DM, DM);
    ln_kernel<<<NTOK, 256>>>(x1, g2, be2, h2);
    mma_gemm<1, 1><<<dim3(DFF / 128, NTOK / 128), 256, GEMM_SMEM>>>(
        h2, w1t, b1, nullptr, nullptr, nullptr, ff, DM, DFF);
    mma_gemm<0, 0><<<dim3(DM / 128, NTOK / 128), 256, GEMM_SMEM>>>(
        ff, w2t, b2, nullptr, nullptr, x1, out, DFF, DM);
}